// round 14
// baseline (speedup 1.0000x reference)
#include <cuda_runtime.h>
#include <cuda_fp16.h>
#include <cstdint>

// Problem constants
#define B_   8
#define S_   1024
#define D_   1024
#define H_   16
#define HD_  64
#define ROWS (B_ * S_)
#define EPS_ 1e-5f

// fp16 GEMM tiling: K chunk 64 fp16 (= 128-byte SW128 rows)
#define BKC    64
#define TILEB  16384
#define NCH    (D_ / BKC)

// LIF borderline fixup
#define TAU    5e-3f
#define FMAX   (1 << 17)

#define SW128(x) ((x) ^ (((x) >> 3) & 0x70))

// ---------------- scratch (device globals) ----------------
__device__ __half g_Xqh[ROWS * D_];
__device__ __half g_Xkh[ROWS * D_];
__device__ __half g_Qb[ROWS * D_];
__device__ __half g_Kb[ROWS * D_];
__device__ __half g_Ath[ROWS * D_];
__device__ __half g_Vh[ROWS * D_];
__device__ __half g_Wq1[D_ * D_];
__device__ __half g_Wk1[D_ * D_];
__device__ __half g_Wv1[D_ * D_];
__device__ __half g_Wo1[D_ * D_];
__device__ unsigned g_qb[ROWS * 32];
__device__ unsigned g_kb[ROWS * 32];
__device__ unsigned g_mb[B_ * 32 * S_];   // mask bits: [b][kchunk][q]
__device__ float    g_mursq[ROWS * 2];
__device__ float    g_mursk[ROWS * 2];
__device__ unsigned g_flagq[FMAX];
__device__ unsigned g_flagk[FMAX];
__device__ int      g_cnt[2];

// ---------------- helpers ----------------
__device__ __forceinline__ uint32_t smem_u32(const void* p) {
    return (uint32_t)__cvta_generic_to_shared(p);
}
__device__ __forceinline__ float mishf(float x) {
    float sp = (x > 20.f) ? x : log1pf(__expf(x));
    return x * tanhf(sp);
}
__device__ __forceinline__ unsigned packh2(__half a, __half b) {
    __half2 t = __halves2half2(a, b);
    return *reinterpret_cast<unsigned*>(&t);
}
__device__ __forceinline__ void ldm4(unsigned* r, const void* p) {
    unsigned addr = smem_u32(p);
    asm volatile("ldmatrix.sync.aligned.m8n8.x4.shared.b16 {%0,%1,%2,%3}, [%4];"
        : "=r"(r[0]), "=r"(r[1]), "=r"(r[2]), "=r"(r[3]) : "r"(addr));
}
__device__ __forceinline__ void ldm4t(unsigned* r, const void* p) {
    unsigned addr = smem_u32(p);
    asm volatile("ldmatrix.sync.aligned.m8n8.x4.trans.shared.b16 {%0,%1,%2,%3}, [%4];"
        : "=r"(r[0]), "=r"(r[1]), "=r"(r[2]), "=r"(r[3]) : "r"(addr));
}
__device__ __forceinline__ void mma16816(float* c, const unsigned* a, unsigned b0, unsigned b1) {
    asm volatile("mma.sync.aligned.m16n8k16.row.col.f32.f16.f16.f32 "
        "{%0,%1,%2,%3}, {%4,%5,%6,%7}, {%8,%9}, {%0,%1,%2,%3};"
        : "+f"(c[0]), "+f"(c[1]), "+f"(c[2]), "+f"(c[3])
        : "r"(a[0]), "r"(a[1]), "r"(a[2]), "r"(a[3]), "r"(b0), "r"(b1));
}
__device__ __forceinline__ void cpa16(uint32_t sa, const void* g) {
    asm volatile("cp.async.cg.shared.global [%0], [%1], 16;" :: "r"(sa), "l"(g));
}

// ---------------- fused prep kernels ----------------
__global__ __launch_bounds__(256)
void prep_w4(const float* __restrict__ Wq, const float* __restrict__ Wk,
             const float* __restrict__ Wv, const float* __restrict__ Wo,
             __half* __restrict__ Oq, __half* __restrict__ Ok,
             __half* __restrict__ Ov, __half* __restrict__ Oo)
{
    int z = blockIdx.y;
    const float* W = (z == 0) ? Wq : ((z == 1) ? Wk : ((z == 2) ? Wv : Wo));
    __half* O = (z == 0) ? Oq : ((z == 1) ? Ok : ((z == 2) ? Ov : Oo));
    int i = blockIdx.x * blockDim.x + threadIdx.x;
    float4 v = ((const float4*)W)[i];
    ((uint2*)O)[i] = make_uint2(packh2(__float2half_rn(v.x), __float2half_rn(v.y)),
                                packh2(__float2half_rn(v.z), __float2half_rn(v.w)));
}

__global__ __launch_bounds__(256)
void prep_bin2(const float* __restrict__ Xq, const float* __restrict__ Xk,
               __half* __restrict__ Yq, __half* __restrict__ Yk)
{
    const float* X = blockIdx.y ? Xk : Xq;
    __half* Y = blockIdx.y ? Yk : Yq;
    int i = blockIdx.x * blockDim.x + threadIdx.x;
    float4 v = ((const float4*)X)[i];
    ((uint2*)Y)[i] = make_uint2(
        packh2(__float2half_rn(v.x >= 2.f ? 1.f : 0.f), __float2half_rn(v.y >= 2.f ? 1.f : 0.f)),
        packh2(__float2half_rn(v.z >= 2.f ? 1.f : 0.f), __float2half_rn(v.w >= 2.f ? 1.f : 0.f)));
}

__global__ __launch_bounds__(256)
void prep_mask(const float* __restrict__ M, unsigned* __restrict__ mb, int* __restrict__ cnt)
{
    int w = blockIdx.x * blockDim.x + threadIdx.x;
    if (w < 2) cnt[w] = 0;
    int b = w >> 15;
    int c = (w >> 10) & 31;
    int q = w & 1023;
    const float4* src = (const float4*)(M + ((size_t)(b * S_ + q)) * S_ + c * 32);
    unsigned word = 0;
#pragma unroll
    for (int i = 0; i < 8; i++) {
        float4 m4 = src[i];
        word |= (m4.x != 0.f ? 1u : 0u) << (i * 4 + 0);
        word |= (m4.y != 0.f ? 1u : 0u) << (i * 4 + 1);
        word |= (m4.z != 0.f ? 1u : 0u) << (i * 4 + 2);
        word |= (m4.w != 0.f ? 1u : 0u) << (i * 4 + 3);
    }
    mb[w] = word;
}

// ---------------- fused 3-in-1 input GEMM (grid.z selects q/k/v), fp16 outputs ----------------
__global__ __launch_bounds__(256, 2)
void gemm3(const __half* __restrict__ Qb, const __half* __restrict__ Kb,
           const __half* __restrict__ Wq1, const __half* __restrict__ Wk1,
           const __half* __restrict__ Wv1,
           const float* __restrict__ bq, const float* __restrict__ bk,
           const float* __restrict__ bv,
           __half* __restrict__ Xqh, __half* __restrict__ Xkh, __half* __restrict__ Vh)
{
    constexpr int S = 3;
    extern __shared__ char raw[];
    char* base = (char*)(((uintptr_t)raw + 1023) & ~(uintptr_t)1023);

    const int z = blockIdx.z;
    const __half* A  = (z == 0) ? Qb : Kb;
    const __half* W0 = (z == 0) ? Wq1 : ((z == 1) ? Wk1 : Wv1);
    const float* bias = (z == 0) ? bq : ((z == 1) ? bk : bv);

    const int tid  = threadIdx.x;
    const int lane = tid & 31;
    const int wid  = tid >> 5;
    const int wm   = wid & 1;
    const int wn   = wid >> 1;
    const int bm   = blockIdx.y * 128;
    const int bn   = blockIdx.x * 128;

    float acc[4][4][4];
#pragma unroll
    for (int i = 0; i < 4; i++)
#pragma unroll
        for (int j = 0; j < 4; j++)
#pragma unroll
            for (int r = 0; r < 4; r++) acc[i][j][r] = 0.f;

    auto load = [&](int c) {
        char* st = base + (c % S) * 2 * TILEB;
        const int k0 = c * BKC;
#pragma unroll
        for (int t = 0; t < 2; t++) {
            const __half* src = (t == 0) ? A : W0;
            const int rb = (t == 0) ? bm : bn;
#pragma unroll
            for (int it = 0; it < 4; it++) {
                int id  = it * 256 + tid;
                int row = id >> 3;
                int ch  = id & 7;
                uint32_t sa = smem_u32(st + t * TILEB + SW128(row * 128 + ch * 16));
                cpa16(sa, src + (size_t)(rb + row) * D_ + k0 + ch * 8);
            }
        }
    };

#pragma unroll
    for (int p = 0; p < S - 1; p++) {
        load(p);
        asm volatile("cp.async.commit_group;" ::: "memory");
    }

    for (int c = 0; c < NCH; c++) {
        asm volatile("cp.async.wait_group %0;" :: "n"(S - 2) : "memory");
        __syncthreads();

        if (c + S - 1 < NCH) load(c + S - 1);
        asm volatile("cp.async.commit_group;" ::: "memory");

        const char* st  = base + (c % S) * 2 * TILEB;
        const char* tA  = st;
        const char* tW0 = st + TILEB;

        const int lr  = lane & 15;
        const int lc8 = (lane >> 4) * 8;

#pragma unroll
        for (int ks = 0; ks < 4; ks++) {
            const int cs2 = (ks * 16 + lc8) * 2;
            unsigned af[4][4];
#pragma unroll
            for (int mi = 0; mi < 4; mi++)
                ldm4(af[mi], tA + SW128((wm * 64 + mi * 16 + lr) * 128 + cs2));
            unsigned b0[2][4];
#pragma unroll
            for (int nb = 0; nb < 2; nb++)
                ldm4(b0[nb], tW0 + SW128((wn * 32 + nb * 16 + lr) * 128 + cs2));
#pragma unroll
            for (int mi = 0; mi < 4; mi++) {
#pragma unroll
                for (int nj = 0; nj < 4; nj++) {
                    const int nb = nj >> 1, sl = nj & 1;
                    mma16816(acc[mi][nj], af[mi], b0[nb][sl], b0[nb][2 + sl]);
                }
            }
        }
    }

    __half* O = (z == 0) ? Xqh : ((z == 1) ? Xkh : Vh);
    const int g = lane >> 2, tg = lane & 3;
#pragma unroll
    for (int mi = 0; mi < 4; mi++) {
#pragma unroll
        for (int nj = 0; nj < 4; nj++) {
            int m0 = bm + wm * 64 + mi * 16 + g;
            int n0 = bn + wn * 32 + nj * 8 + tg * 2;
            float2 bs = *(const float2*)(bias + n0);
            float v0 = acc[mi][nj][0] + bs.x;
            float v1 = acc[mi][nj][1] + bs.y;
            float v2 = acc[mi][nj][2] + bs.x;
            float v3 = acc[mi][nj][3] + bs.y;
            *(unsigned*)(O + (size_t)m0 * D_ + n0) =
                packh2(__float2half_rn(v0), __float2half_rn(v1));
            *(unsigned*)(O + (size_t)(m0 + 8) * D_ + n0) =
                packh2(__float2half_rn(v2), __float2half_rn(v3));
        }
    }
}

// ---------------- output GEMM (mish + fp16 residual epilogue) ----------------
template<int S>
__global__ __launch_bounds__(256, 2)
void hgemm_o(const __half* __restrict__ A, const __half* __restrict__ W0,
             const float* __restrict__ bias, const __half* __restrict__ resid,
             float* __restrict__ C)
{
    extern __shared__ char raw[];
    char* base = (char*)(((uintptr_t)raw + 1023) & ~(uintptr_t)1023);

    const int tid  = threadIdx.x;
    const int lane = tid & 31;
    const int wid  = tid >> 5;
    const int wm   = wid & 1;
    const int wn   = wid >> 1;
    const int bm   = blockIdx.y * 128;
    const int bn   = blockIdx.x * 128;

    float acc[4][4][4];
#pragma unroll
    for (int i = 0; i < 4; i++)
#pragma unroll
        for (int j = 0; j < 4; j++)
#pragma unroll
            for (int r = 0; r < 4; r++) acc[i][j][r] = 0.f;

    auto load = [&](int c) {
        char* st = base + (c % S) * 2 * TILEB;
        const int k0 = c * BKC;
#pragma unroll
        for (int t = 0; t < 2; t++) {
            const __half* src = (t == 0) ? A : W0;
            const int rb = (t == 0) ? bm : bn;
#pragma unroll
            for (int it = 0; it < 4; it++) {
                int id  = it * 256 + tid;
                int row = id >> 3;
                int ch  = id & 7;
                uint32_t sa = smem_u32(st + t * TILEB + SW128(row * 128 + ch * 16));
                cpa16(sa, src + (size_t)(rb + row) * D_ + k0 + ch * 8);
            }
        }
    };

#pragma unroll
    for (int p = 0; p < S - 1; p++) {
        load(p);
        asm volatile("cp.async.commit_group;" ::: "memory");
    }

    for (int c = 0; c < NCH; c++) {
        asm volatile("cp.async.wait_group %0;" :: "n"(S - 2) : "memory");
        __syncthreads();

        if (c + S - 1 < NCH) load(c + S - 1);
        asm volatile("cp.async.commit_group;" ::: "memory");

        const char* st  = base + (c % S) * 2 * TILEB;
        const char* tA  = st;
        const char* tW0 = st + TILEB;

        const int lr  = lane & 15;
        const int lc8 = (lane >> 4) * 8;

#pragma unroll
        for (int ks = 0; ks < 4; ks++) {
            const int cs2 = (ks * 16 + lc8) * 2;
            unsigned af[4][4];
#pragma unroll
            for (int mi = 0; mi < 4; mi++)
                ldm4(af[mi], tA + SW128((wm * 64 + mi * 16 + lr) * 128 + cs2));
            unsigned b0[2][4];
#pragma unroll
            for (int nb = 0; nb < 2; nb++)
                ldm4(b0[nb], tW0 + SW128((wn * 32 + nb * 16 + lr) * 128 + cs2));
#pragma unroll
            for (int mi = 0; mi < 4; mi++) {
#pragma unroll
                for (int nj = 0; nj < 4; nj++) {
                    const int nb = nj >> 1, sl = nj & 1;
                    mma16816(acc[mi][nj], af[mi], b0[nb][sl], b0[nb][2 + sl]);
                }
            }
        }
    }

    const int g = lane >> 2, tg = lane & 3;
#pragma unroll
    for (int mi = 0; mi < 4; mi++) {
#pragma unroll
        for (int nj = 0; nj < 4; nj++) {
            int m0 = bm + wm * 64 + mi * 16 + g;
            int n0 = bn + wn * 32 + nj * 8 + tg * 2;
            float2 bs = *(const float2*)(bias + n0);
            __half2 r0 = *(const __half2*)(resid + (size_t)m0 * D_ + n0);
            __half2 r1 = *(const __half2*)(resid + (size_t)(m0 + 8) * D_ + n0);
            float v0 = __half2float(r0.x) + mishf(acc[mi][nj][0] + bs.x);
            float v1 = __half2float(r0.y) + mishf(acc[mi][nj][1] + bs.y);
            float v2 = __half2float(r1.x) + mishf(acc[mi][nj][2] + bs.x);
            float v3 = __half2float(r1.y) + mishf(acc[mi][nj][3] + bs.y);
            *(float2*)(C + (size_t)m0 * D_ + n0)       = make_float2(v0, v1);
            *(float2*)(C + (size_t)(m0 + 8) * D_ + n0) = make_float2(v2, v3);
        }
    }
}

// ---------------- fused LayerNorm + LIF + bit-pack + flagging (fp16 X; grid.y: q/k) ----------------
__global__ __launch_bounds__(256)
void ln_lif2(const __half* __restrict__ Xq, const __half* __restrict__ Xk,
             const float* __restrict__ gq, const float* __restrict__ beq,
             const float* __restrict__ gk, const float* __restrict__ bek,
             unsigned* __restrict__ bq_, unsigned* __restrict__ bk_,
             float* __restrict__ mursq, float* __restrict__ mursk,
             unsigned* __restrict__ flagq, unsigned* __restrict__ flagk,
             int* __restrict__ cnt)
{
    const int zz = blockIdx.y;
    const __half* X = zz ? Xk : Xq;
    const float* gamma = zz ? gk : gq;
    const float* beta  = zz ? bek : beq;
    unsigned* bits = zz ? bk_ : bq_;
    float* murs = zz ? mursk : mursq;
    unsigned* flags = zz ? flagk : flagq;
    int* cp = cnt + zz;

    const int row  = blockIdx.x;
    const int t    = threadIdx.x;
    const int lane = t & 31;
    const int wid  = t >> 5;

    const __half* xr = X + (size_t)row * D_;

    float x[4];
    float s = 0.f, sq = 0.f;
#pragma unroll
    for (int i = 0; i < 4; i++) {
        x[i] = __half2float(xr[i * 256 + t]);
        s  += x[i];
        sq += x[i] * x[i];
    }
#pragma unroll
    for (int off = 16; off > 0; off >>= 1) {
        s  += __shfl_xor_sync(0xffffffffu, s,  off);
        sq += __shfl_xor_sync(0xffffffffu, sq, off);
    }
    __shared__ float ss[8], sqq[8];
    __shared__ float s_mu, s_rs;
    if (lane == 0) { ss[wid] = s; sqq[wid] = sq; }
    __syncthreads();
    if (wid == 0) {
        float a = (lane < 8) ? ss[lane]  : 0.f;
        float b = (lane < 8) ? sqq[lane] : 0.f;
#pragma unroll
        for (int off = 4; off > 0; off >>= 1) {
            a += __shfl_xor_sync(0xffffffffu, a, off);
            b += __shfl_xor_sync(0xffffffffu, b, off);
        }
        if (lane == 0) {
            float mu  = a * (1.f / D_);
            float var = b * (1.f / D_) - mu * mu;
            s_mu = mu;
            s_rs = rsqrtf(var + EPS_);
            murs[row * 2 + 0] = mu;
            murs[row * 2 + 1] = s_rs;
        }
    }
    __syncthreads();
    const float mu = s_mu, rs = s_rs;

#pragma unroll
    for (int i = 0; i < 4; i++) {
        int d = i * 256 + t;
        float y = (x[i] - mu) * rs * gamma[d] + beta[d];
        unsigned word = __ballot_sync(0xffffffffu, y >= 2.0f);
        if (lane == 0) bits[(size_t)row * 32 + i * 8 + wid] = word;
        if (fabsf(y - 2.0f) < TAU) {
            int idx = atomicAdd(cp, 1);
            if (idx < FMAX) flags[idx] = ((unsigned)row << 10) | (unsigned)d;
        }
    }
}

// ---------------- fused exact fixup (grid.y: q/k) ----------------
#define FIX_WARPS 2048
__global__ __launch_bounds__(128)
void fixup2(const float* __restrict__ Q, const float* __restrict__ K_,
            const float* __restrict__ Wq, const float* __restrict__ Wk,
            const float* __restrict__ bq_, const float* __restrict__ bk_,
            const float* __restrict__ gq, const float* __restrict__ beq,
            const float* __restrict__ gk, const float* __restrict__ bek,
            const float* __restrict__ mursq, const float* __restrict__ mursk,
            const unsigned* __restrict__ flagq, const unsigned* __restrict__ flagk,
            const int* __restrict__ cnt,
            unsigned* __restrict__ bitsq, unsigned* __restrict__ bitsk)
{
    const int zz = blockIdx.y;
    const float* Xsrc = zz ? K_ : Q;
    const float* W = zz ? Wk : Wq;
    const float* bias = zz ? bk_ : bq_;
    const float* gamma = zz ? gk : gq;
    const float* beta = zz ? bek : beq;
    const float* murs = zz ? mursk : mursq;
    const unsigned* flags = zz ? flagk : flagq;
    unsigned* bits = zz ? bitsk : bitsq;

    const int wgid = (blockIdx.x * 128 + threadIdx.x) >> 5;
    const int lane = threadIdx.x & 31;
    int n = cnt[zz];
    if (n > FMAX) n = FMAX;

    for (int i = wgid; i < n; i += FIX_WARPS) {
        unsigned f = flags[i];
        int row = f >> 10, col = f & 1023;
        const float* xr = Xsrc + (size_t)row * D_;
        const float* wr = W + (size_t)col * D_;
        float s = 0.f;
#pragma unroll 4
        for (int k = lane; k < D_; k += 32)
            if (xr[k] >= 2.f) s += wr[k];
#pragma unroll
        for (int off = 16; off > 0; off >>= 1)
            s += __shfl_xor_sync(0xffffffffu, s, off);
        if (lane == 0) {
            float mu = murs[row * 2 + 0], rs = murs[row * 2 + 1];
            float y = (s + bias[col] - mu) * rs * gamma[col] + beta[col];
            unsigned m = 1u << (col & 31);
            unsigned* wp = &bits[(size_t)row * 32 + (col >> 5)];
            if (y >= 2.f) atomicOr(wp, m);
            else          atomicAnd(wp, ~m);
        }
    }
}

// ---------------- HMMA flash attention: double-buffered P, 1 sync/chunk ----------------
#define AT_PH   0                       // half [2][128][40]    20480
#define AT_VH   20480                   // half [2][32][72]      9216
#define AT_KB   29696                   // unsigned [1024][2]    8192
#define AT_SUM  37888                   // float [128]            512
#define AT_LUT  38400                   // float [65]             272
#define AT_SMEM (38672 + 1024)

__global__ __launch_bounds__(128, 4)
void attn_kernel(const unsigned* __restrict__ qbits, const unsigned* __restrict__ kbits,
                 const __half* __restrict__ Vh,
                 const unsigned* __restrict__ mbits,
                 __half* __restrict__ outh)
{
    extern __shared__ char raw[];
    char* sb = (char*)(((uintptr_t)raw + 1023) & ~(uintptr_t)1023);
    __half*   sPh  = (__half*)(sb + AT_PH);    // [2][128][40]
    __half*   sVh  = (__half*)(sb + AT_VH);    // [2][32][72]
    unsigned* sKb  = (unsigned*)(sb + AT_KB);  // [1024][2]
    float*    sSum = (float*)(sb + AT_SUM);
    float*    sLut = (float*)(sb + AT_LUT);

    const int qblk = blockIdx.x;
    const int h    = blockIdx.y;
    const int b    = blockIdx.z;
    const int t    = threadIdx.x;
    const int lane = t & 31;
    const int wid  = t >> 5;

    const uint2 qww = *(const uint2*)&qbits[((size_t)(b * S_ + qblk * 128 + t)) * 32 + h * 2];
    const unsigned long long q01 = ((unsigned long long)qww.y << 32) | qww.x;

    float acc[2][8][4];
#pragma unroll
    for (int i = 0; i < 2; i++)
#pragma unroll
        for (int j = 0; j < 8; j++)
#pragma unroll
            for (int r = 0; r < 4; r++) acc[i][j][r] = 0.f;
    float ssum = 0.f;

    auto loadV = [&](int c) {
        __half* dvh = sVh + (c & 1) * 32 * 72;
        const size_t gb = ((size_t)(b * S_ + c * 32)) * D_ + h * HD_;
#pragma unroll
        for (int i = 0; i < 2; i++) {
            int id = i * 128 + t;
            int r  = id >> 3, ch = id & 7;
            cpa16(smem_u32(dvh + r * 72 + ch * 8), Vh + gb + (size_t)r * D_ + ch * 8);
        }
    };

    // e-compute for chunk cc into buffer cc&1 (thread t owns q-row t)
    auto compE = [&](int cc, unsigned mwv) {
        __half* ph = sPh + (cc & 1) * 128 * 40 + t * 40;
        const int k0 = cc * 32;
        const unsigned long long* kb64 = (const unsigned long long*)sKb;
#pragma unroll
        for (int j = 0; j < 32; j += 2) {
            int s0 = __popcll(q01 & kb64[k0 + j]);
            int s1 = __popcll(q01 & kb64[k0 + j + 1]);
            float e0 = sLut[s0 * (int)((mwv >> j) & 1u)];
            float e1 = sLut[s1 * (int)((mwv >> (j + 1)) & 1u)];
            __half h0 = __float2half_rn(e0), h1 = __float2half_rn(e1);
            ssum += __half2float(h0) + __half2float(h1);
            *(unsigned*)(ph + j) = packh2(h0, h1);
        }
    };

    // preload K bits + LUT
#pragma unroll
    for (int i = 0; i < 8; i++) {
        int j = i * 128 + t;
        *(uint2*)&sKb[j * 2] = *(const uint2*)&kbits[((size_t)(b * S_ + j)) * 32 + h * 2];
    }
    if (t < 65) sLut[t] = __expf((float)t * 0.125f);

    loadV(0);
    asm volatile("cp.async.commit_group;" ::: "memory");

    const unsigned* mrow = mbits + b * 32 * S_ + qblk * 128 + t;
    unsigned mw = mrow[0];
    __syncthreads();                    // sKb/sLut visible

    compE(0, mw);
    mw = mrow[S_];                      // chunk 1 mask
    __syncthreads();                    // sPh[0] visible

    for (int c = 0; c < 32; c++) {
        if (c + 1 < 32) loadV(c + 1);
        asm volatile("cp.async.commit_group;" ::: "memory");

        // compute e(c+1) into the other P buffer (overlaps V latency + MMA issue)
        if (c + 1 < 32) {
            compE(c + 1, mw);
            mw = (c + 2 < 32) ? mrow[(size_t)(c + 2) * S_] : 0u;
        }

        asm volatile("cp.async.wait_group 1;" ::: "memory");   // V(c) ready

        // MMA: P(c)[128x32] @ V(c)[32x64]
        const __half* phb = sPh + (c & 1) * 128 * 40;
        const __half* vhb = sVh + (c & 1) * 32 * 72;
        const int lr  = lane & 15;
        const int lc8 = (lane >> 4) * 8;
        const int l8  = lane & 7;
        const int ks8 = ((lane >> 3) & 1) * 8;
        const int ns8 = (lane >> 4) * 8;
#pragma unroll
        for (int kk = 0; kk < 2; kk++) {
            unsigned ah[2][4];
#pragma unroll
            for (int mi = 0; mi < 2; mi++) {
                const int rofs = (wid * 32 + mi * 16 + lr) * 40 + kk * 16 + lc8;
                ldm4(ah[mi], phb + rofs);
            }
            unsigned vh[4][4];
#pragma unroll
            for (int nb = 0; nb < 4; nb++) {
                const int vofs = (kk * 16 + ks8 + l8) * 72 + nb * 16 + ns8;
                ldm4t(vh[nb], vhb + vofs);
            }
#pragma unroll
            for (int mi = 0; mi < 2; mi++) {
#pragma unroll
                for (int nj = 0; nj < 8; nj++) {
                    const int nb = nj >> 1, half = nj & 1;
                    mma16816(acc[mi][nj], ah[mi], vh[nb][half * 2], vh[nb][half * 2 + 1]);
                }
            }
        }
        __syncthreads();   // P(c+1) visible to all; P(c) buffer free for e(c+2)
    }

    sSum[t] = ssum;
    __syncthreads();

    const int g = lane >> 2, tg = lane & 3;
#pragma unroll
    for (int mi = 0; mi < 2; mi++) {
        const int qr0 = wid * 32 + mi * 16 + g;
        const float inv0 = 1.f / sSum[qr0];
        const float inv1 = 1.f / sSum[qr0 + 8];
        const size_t base0 = ((size_t)(b * S_ + qblk * 128 + qr0)) * D_ + h * HD_;
#pragma unroll
        for (int nj = 0; nj < 8; nj++) {
            const int n = nj * 8 + tg * 2;
            float v0 = acc[mi][nj][0] * inv0;
            float v1 = acc[mi][nj][1] * inv0;
            float v2 = acc[mi][nj][2] * inv1;
            float v3 = acc[mi][nj][3] * inv1;
            *(unsigned*)(outh + base0 + n)          = packh2(__float2half_rn(v0), __float2half_rn(v1));
            *(unsigned*)(outh + base0 + 8 * D_ + n) = packh2(__float2half_rn(v2), __float2half_rn(v3));
        }
    }
}

// ---------------- launch ----------------
extern "C" void kernel_launch(void* const* d_in, const int* in_sizes, int n_in,
                              void* d_out, int out_size)
{
    const float* Q   = (const float*)d_in[0];
    const float* K_  = (const float*)d_in[1];
    const float* adj = (const float*)d_in[2];
    const float* Wq  = (const float*)d_in[3];
    const float* bq  = (const float*)d_in[4];
    const float* Wk  = (const float*)d_in[5];
    const float* bk  = (const float*)d_in[6];
    const float* Wv  = (const float*)d_in[7];
    const float* bv  = (const float*)d_in[8];
    const float* Wo  = (const float*)d_in[9];
    const float* bo  = (const float*)d_in[10];
    const float* gq  = (const float*)d_in[11];
    const float* beq = (const float*)d_in[12];
    const float* gk  = (const float*)d_in[13];
    const float* bek = (const float*)d_in[14];
    float* out = (float*)d_out;

    float *mursq, *mursk;
    __half *Xqh, *Xkh, *Qb, *Kb, *Ath, *Vh, *Wq1, *Wk1, *Wv1, *Wo1;
    unsigned *qb, *kb, *mb, *flagq, *flagk;
    int* cnt;
    cudaGetSymbolAddress((void**)&Xqh,  g_Xqh);
    cudaGetSymbolAddress((void**)&Xkh,  g_Xkh);
    cudaGetSymbolAddress((void**)&Qb,   g_Qb);
    cudaGetSymbolAddress((void**)&Kb,   g_Kb);
    cudaGetSymbolAddress((void**)&Ath,  g_Ath);
    cudaGetSymbolAddress((void**)&Vh,   g_Vh);
    cudaGetSymbolAddress((void**)&Wq1,  g_Wq1);
    cudaGetSymbolAddress((void**)&Wk1,  g_Wk1);
    cudaGetSymbolAddress((void**)&Wv1,  g_Wv1);
    cudaGetSymbolAddress((void**)&Wo1,  g_Wo1);
    cudaGetSymbolAddress((void**)&qb,   g_qb);
    cudaGetSymbolAddress((void**)&kb,   g_kb);
    cudaGetSymbolAddress((void**)&mb,   g_mb);
    cudaGetSymbolAddress((void**)&mursq, g_mursq);
    cudaGetSymbolAddress((void**)&mursk, g_mursk);
    cudaGetSymbolAddress((void**)&flagq, g_flagq);
    cudaGetSymbolAddress((void**)&flagk, g_flagk);
    cudaGetSymbolAddress((void**)&cnt,   g_cnt);

    const int smem1 = 3 * 2 * TILEB + 1024;   // 99328 (S=3, 2 tiles)
    cudaFuncSetAttribute((const void*)gemm3,
                         cudaFuncAttributeMaxDynamicSharedMemorySize, smem1);
    cudaFuncSetAttribute((const void*)hgemm_o<3>,
                         cudaFuncAttributeMaxDynamicSharedMemorySize, smem1);
    cudaFuncSetAttribute((const void*)attn_kernel,
                         cudaFuncAttributeMaxDynamicSharedMemorySize, AT_SMEM);

    const int WELEM = D_ * D_;
    prep_w4<<<dim3(WELEM / 4 / 256, 4), 256>>>(Wq, Wk, Wv, Wo, Wq1, Wk1, Wv1, Wo1);
    prep_bin2<<<dim3(ROWS * D_ / 4 / 256, 2), 256>>>(Q, K_, Qb, Kb);
    prep_mask<<<B_ * 32 * S_ / 256, 256>>>(adj, mb, cnt);

    gemm3<<<dim3(D_ / 128, ROWS / 128, 3), 256, smem1>>>(
        Qb, Kb, Wq1, Wk1, Wv1, bq, bk, bv, Xqh, Xkh, Vh);

    ln_lif2<<<dim3(ROWS, 2), 256>>>(Xqh, Xkh, gq, beq, gk, bek,
                                    qb, kb, mursq, mursk, flagq, flagk, cnt);

    fixup2<<<dim3(FIX_WARPS / 4, 2), 128>>>(Q, K_, Wq, Wk, bq, bk,
                                            gq, beq, gk, bek, mursq, mursk,
                                            flagq, flagk, cnt, qb, kb);

    attn_kernel<<<dim3(8, H_, B_), 128, AT_SMEM>>>(qb, kb, Vh, mb, Ath);

    hgemm_o<3><<<dim3(D_ / 128, ROWS / 128), 256, smem1>>>(Ath, Wo1, bo, Ath, out);
}

// round 15
// speedup vs baseline: 1.5021x; 1.5021x over previous
#include <cuda_runtime.h>
#include <cuda_fp16.h>
#include <cstdint>

// Problem constants
#define B_   8
#define S_   1024
#define D_   1024
#define H_   16
#define HD_  64
#define ROWS (B_ * S_)
#define EPS_ 1e-5f

// fp16 GEMM tiling: K chunk 64 fp16 (= 128-byte SW128 rows)
#define BKC    64
#define TILEB  16384
#define NCH    (D_ / BKC)

// LIF borderline fixup
#define TAU    5e-3f
#define FMAX   (1 << 17)

#define SW128(x) ((x) ^ (((x) >> 3) & 0x70))

// ---------------- scratch (device globals) ----------------
__device__ __half g_Xqh[ROWS * D_];
__device__ __half g_Xkh[ROWS * D_];
__device__ __half g_Qb[ROWS * D_];
__device__ __half g_Kb[ROWS * D_];
__device__ __half g_Ath[ROWS * D_];
__device__ __half g_Vh[ROWS * D_];
__device__ __half g_Wq1[D_ * D_];
__device__ __half g_Wk1[D_ * D_];
__device__ __half g_Wv1[D_ * D_];
__device__ __half g_Wo1[D_ * D_];
__device__ unsigned g_qb[ROWS * 32];
__device__ unsigned g_kb[ROWS * 32];
__device__ unsigned g_mb[B_ * 32 * S_];   // mask bits: [b][kchunk][q]
__device__ float    g_mursq[ROWS * 2];
__device__ float    g_mursk[ROWS * 2];
__device__ unsigned g_flagq[FMAX];
__device__ unsigned g_flagk[FMAX];
__device__ int      g_cnt[2];

// ---------------- helpers ----------------
__device__ __forceinline__ uint32_t smem_u32(const void* p) {
    return (uint32_t)__cvta_generic_to_shared(p);
}
__device__ __forceinline__ float mishf(float x) {
    float sp = (x > 20.f) ? x : log1pf(__expf(x));
    return x * tanhf(sp);
}
__device__ __forceinline__ unsigned packh2(__half a, __half b) {
    __half2 t = __halves2half2(a, b);
    return *reinterpret_cast<unsigned*>(&t);
}
__device__ __forceinline__ void ldm4(unsigned* r, const void* p) {
    unsigned addr = smem_u32(p);
    asm volatile("ldmatrix.sync.aligned.m8n8.x4.shared.b16 {%0,%1,%2,%3}, [%4];"
        : "=r"(r[0]), "=r"(r[1]), "=r"(r[2]), "=r"(r[3]) : "r"(addr));
}
__device__ __forceinline__ void ldm4t(unsigned* r, const void* p) {
    unsigned addr = smem_u32(p);
    asm volatile("ldmatrix.sync.aligned.m8n8.x4.trans.shared.b16 {%0,%1,%2,%3}, [%4];"
        : "=r"(r[0]), "=r"(r[1]), "=r"(r[2]), "=r"(r[3]) : "r"(addr));
}
__device__ __forceinline__ void mma16816(float* c, const unsigned* a, unsigned b0, unsigned b1) {
    asm volatile("mma.sync.aligned.m16n8k16.row.col.f32.f16.f16.f32 "
        "{%0,%1,%2,%3}, {%4,%5,%6,%7}, {%8,%9}, {%0,%1,%2,%3};"
        : "+f"(c[0]), "+f"(c[1]), "+f"(c[2]), "+f"(c[3])
        : "r"(a[0]), "r"(a[1]), "r"(a[2]), "r"(a[3]), "r"(b0), "r"(b1));
}
__device__ __forceinline__ void cpa16(uint32_t sa, const void* g) {
    asm volatile("cp.async.cg.shared.global [%0], [%1], 16;" :: "r"(sa), "l"(g));
}

// ---------------- fused prep kernels ----------------
__global__ __launch_bounds__(256)
void prep_w4(const float* __restrict__ Wq, const float* __restrict__ Wk,
             const float* __restrict__ Wv, const float* __restrict__ Wo,
             __half* __restrict__ Oq, __half* __restrict__ Ok,
             __half* __restrict__ Ov, __half* __restrict__ Oo)
{
    int z = blockIdx.y;
    const float* W = (z == 0) ? Wq : ((z == 1) ? Wk : ((z == 2) ? Wv : Wo));
    __half* O = (z == 0) ? Oq : ((z == 1) ? Ok : ((z == 2) ? Ov : Oo));
    int i = blockIdx.x * blockDim.x + threadIdx.x;
    float4 v = ((const float4*)W)[i];
    ((uint2*)O)[i] = make_uint2(packh2(__float2half_rn(v.x), __float2half_rn(v.y)),
                                packh2(__float2half_rn(v.z), __float2half_rn(v.w)));
}

__global__ __launch_bounds__(256)
void prep_bin2(const float* __restrict__ Xq, const float* __restrict__ Xk,
               __half* __restrict__ Yq, __half* __restrict__ Yk)
{
    const float* X = blockIdx.y ? Xk : Xq;
    __half* Y = blockIdx.y ? Yk : Yq;
    int i = blockIdx.x * blockDim.x + threadIdx.x;
    float4 v = ((const float4*)X)[i];
    ((uint2*)Y)[i] = make_uint2(
        packh2(__float2half_rn(v.x >= 2.f ? 1.f : 0.f), __float2half_rn(v.y >= 2.f ? 1.f : 0.f)),
        packh2(__float2half_rn(v.z >= 2.f ? 1.f : 0.f), __float2half_rn(v.w >= 2.f ? 1.f : 0.f)));
}

__global__ __launch_bounds__(256)
void prep_mask(const float* __restrict__ M, unsigned* __restrict__ mb, int* __restrict__ cnt)
{
    int w = blockIdx.x * blockDim.x + threadIdx.x;
    if (w < 2) cnt[w] = 0;
    int b = w >> 15;
    int c = (w >> 10) & 31;
    int q = w & 1023;
    const float4* src = (const float4*)(M + ((size_t)(b * S_ + q)) * S_ + c * 32);
    unsigned word = 0;
#pragma unroll
    for (int i = 0; i < 8; i++) {
        float4 m4 = src[i];
        word |= (m4.x != 0.f ? 1u : 0u) << (i * 4 + 0);
        word |= (m4.y != 0.f ? 1u : 0u) << (i * 4 + 1);
        word |= (m4.z != 0.f ? 1u : 0u) << (i * 4 + 2);
        word |= (m4.w != 0.f ? 1u : 0u) << (i * 4 + 3);
    }
    mb[w] = word;
}

// ---------------- fused 3-in-1 input GEMM (grid.z selects q/k/v), fp16 outputs ----------------
__global__ __launch_bounds__(256, 2)
void gemm3(const __half* __restrict__ Qb, const __half* __restrict__ Kb,
           const __half* __restrict__ Wq1, const __half* __restrict__ Wk1,
           const __half* __restrict__ Wv1,
           const float* __restrict__ bq, const float* __restrict__ bk,
           const float* __restrict__ bv,
           __half* __restrict__ Xqh, __half* __restrict__ Xkh, __half* __restrict__ Vh)
{
    constexpr int S = 3;
    extern __shared__ char raw[];
    char* base = (char*)(((uintptr_t)raw + 1023) & ~(uintptr_t)1023);

    const int z = blockIdx.z;
    const __half* A  = (z == 0) ? Qb : Kb;
    const __half* W0 = (z == 0) ? Wq1 : ((z == 1) ? Wk1 : Wv1);
    const float* bias = (z == 0) ? bq : ((z == 1) ? bk : bv);

    const int tid  = threadIdx.x;
    const int lane = tid & 31;
    const int wid  = tid >> 5;
    const int wm   = wid & 1;
    const int wn   = wid >> 1;
    const int bm   = blockIdx.y * 128;
    const int bn   = blockIdx.x * 128;

    float acc[4][4][4];
#pragma unroll
    for (int i = 0; i < 4; i++)
#pragma unroll
        for (int j = 0; j < 4; j++)
#pragma unroll
            for (int r = 0; r < 4; r++) acc[i][j][r] = 0.f;

    auto load = [&](int c) {
        char* st = base + (c % S) * 2 * TILEB;
        const int k0 = c * BKC;
#pragma unroll
        for (int t = 0; t < 2; t++) {
            const __half* src = (t == 0) ? A : W0;
            const int rb = (t == 0) ? bm : bn;
#pragma unroll
            for (int it = 0; it < 4; it++) {
                int id  = it * 256 + tid;
                int row = id >> 3;
                int ch  = id & 7;
                uint32_t sa = smem_u32(st + t * TILEB + SW128(row * 128 + ch * 16));
                cpa16(sa, src + (size_t)(rb + row) * D_ + k0 + ch * 8);
            }
        }
    };

#pragma unroll
    for (int p = 0; p < S - 1; p++) {
        load(p);
        asm volatile("cp.async.commit_group;" ::: "memory");
    }

    for (int c = 0; c < NCH; c++) {
        asm volatile("cp.async.wait_group %0;" :: "n"(S - 2) : "memory");
        __syncthreads();

        if (c + S - 1 < NCH) load(c + S - 1);
        asm volatile("cp.async.commit_group;" ::: "memory");

        const char* st  = base + (c % S) * 2 * TILEB;
        const char* tA  = st;
        const char* tW0 = st + TILEB;

        const int lr  = lane & 15;
        const int lc8 = (lane >> 4) * 8;

#pragma unroll
        for (int ks = 0; ks < 4; ks++) {
            const int cs2 = (ks * 16 + lc8) * 2;
            unsigned af[4][4];
#pragma unroll
            for (int mi = 0; mi < 4; mi++)
                ldm4(af[mi], tA + SW128((wm * 64 + mi * 16 + lr) * 128 + cs2));
            unsigned b0[2][4];
#pragma unroll
            for (int nb = 0; nb < 2; nb++)
                ldm4(b0[nb], tW0 + SW128((wn * 32 + nb * 16 + lr) * 128 + cs2));
#pragma unroll
            for (int mi = 0; mi < 4; mi++) {
#pragma unroll
                for (int nj = 0; nj < 4; nj++) {
                    const int nb = nj >> 1, sl = nj & 1;
                    mma16816(acc[mi][nj], af[mi], b0[nb][sl], b0[nb][2 + sl]);
                }
            }
        }
    }

    __half* O = (z == 0) ? Xqh : ((z == 1) ? Xkh : Vh);
    const int g = lane >> 2, tg = lane & 3;
#pragma unroll
    for (int mi = 0; mi < 4; mi++) {
#pragma unroll
        for (int nj = 0; nj < 4; nj++) {
            int m0 = bm + wm * 64 + mi * 16 + g;
            int n0 = bn + wn * 32 + nj * 8 + tg * 2;
            float2 bs = *(const float2*)(bias + n0);
            float v0 = acc[mi][nj][0] + bs.x;
            float v1 = acc[mi][nj][1] + bs.y;
            float v2 = acc[mi][nj][2] + bs.x;
            float v3 = acc[mi][nj][3] + bs.y;
            *(unsigned*)(O + (size_t)m0 * D_ + n0) =
                packh2(__float2half_rn(v0), __float2half_rn(v1));
            *(unsigned*)(O + (size_t)(m0 + 8) * D_ + n0) =
                packh2(__float2half_rn(v2), __float2half_rn(v3));
        }
    }
}

// ---------------- output GEMM (mish + fp16 residual epilogue) ----------------
template<int S>
__global__ __launch_bounds__(256, 2)
void hgemm_o(const __half* __restrict__ A, const __half* __restrict__ W0,
             const float* __restrict__ bias, const __half* __restrict__ resid,
             float* __restrict__ C)
{
    extern __shared__ char raw[];
    char* base = (char*)(((uintptr_t)raw + 1023) & ~(uintptr_t)1023);

    const int tid  = threadIdx.x;
    const int lane = tid & 31;
    const int wid  = tid >> 5;
    const int wm   = wid & 1;
    const int wn   = wid >> 1;
    const int bm   = blockIdx.y * 128;
    const int bn   = blockIdx.x * 128;

    float acc[4][4][4];
#pragma unroll
    for (int i = 0; i < 4; i++)
#pragma unroll
        for (int j = 0; j < 4; j++)
#pragma unroll
            for (int r = 0; r < 4; r++) acc[i][j][r] = 0.f;

    auto load = [&](int c) {
        char* st = base + (c % S) * 2 * TILEB;
        const int k0 = c * BKC;
#pragma unroll
        for (int t = 0; t < 2; t++) {
            const __half* src = (t == 0) ? A : W0;
            const int rb = (t == 0) ? bm : bn;
#pragma unroll
            for (int it = 0; it < 4; it++) {
                int id  = it * 256 + tid;
                int row = id >> 3;
                int ch  = id & 7;
                uint32_t sa = smem_u32(st + t * TILEB + SW128(row * 128 + ch * 16));
                cpa16(sa, src + (size_t)(rb + row) * D_ + k0 + ch * 8);
            }
        }
    };

#pragma unroll
    for (int p = 0; p < S - 1; p++) {
        load(p);
        asm volatile("cp.async.commit_group;" ::: "memory");
    }

    for (int c = 0; c < NCH; c++) {
        asm volatile("cp.async.wait_group %0;" :: "n"(S - 2) : "memory");
        __syncthreads();

        if (c + S - 1 < NCH) load(c + S - 1);
        asm volatile("cp.async.commit_group;" ::: "memory");

        const char* st  = base + (c % S) * 2 * TILEB;
        const char* tA  = st;
        const char* tW0 = st + TILEB;

        const int lr  = lane & 15;
        const int lc8 = (lane >> 4) * 8;

#pragma unroll
        for (int ks = 0; ks < 4; ks++) {
            const int cs2 = (ks * 16 + lc8) * 2;
            unsigned af[4][4];
#pragma unroll
            for (int mi = 0; mi < 4; mi++)
                ldm4(af[mi], tA + SW128((wm * 64 + mi * 16 + lr) * 128 + cs2));
            unsigned b0[2][4];
#pragma unroll
            for (int nb = 0; nb < 2; nb++)
                ldm4(b0[nb], tW0 + SW128((wn * 32 + nb * 16 + lr) * 128 + cs2));
#pragma unroll
            for (int mi = 0; mi < 4; mi++) {
#pragma unroll
                for (int nj = 0; nj < 4; nj++) {
                    const int nb = nj >> 1, sl = nj & 1;
                    mma16816(acc[mi][nj], af[mi], b0[nb][sl], b0[nb][2 + sl]);
                }
            }
        }
    }

    const int g = lane >> 2, tg = lane & 3;
#pragma unroll
    for (int mi = 0; mi < 4; mi++) {
#pragma unroll
        for (int nj = 0; nj < 4; nj++) {
            int m0 = bm + wm * 64 + mi * 16 + g;
            int n0 = bn + wn * 32 + nj * 8 + tg * 2;
            float2 bs = *(const float2*)(bias + n0);
            __half2 r0 = *(const __half2*)(resid + (size_t)m0 * D_ + n0);
            __half2 r1 = *(const __half2*)(resid + (size_t)(m0 + 8) * D_ + n0);
            float v0 = __half2float(r0.x) + mishf(acc[mi][nj][0] + bs.x);
            float v1 = __half2float(r0.y) + mishf(acc[mi][nj][1] + bs.y);
            float v2 = __half2float(r1.x) + mishf(acc[mi][nj][2] + bs.x);
            float v3 = __half2float(r1.y) + mishf(acc[mi][nj][3] + bs.y);
            *(float2*)(C + (size_t)m0 * D_ + n0)       = make_float2(v0, v1);
            *(float2*)(C + (size_t)(m0 + 8) * D_ + n0) = make_float2(v2, v3);
        }
    }
}

// ---------------- fused LayerNorm + LIF + bit-pack + flagging (fp16 X; grid.y: q/k) ----------------
__global__ __launch_bounds__(256)
void ln_lif2(const __half* __restrict__ Xq, const __half* __restrict__ Xk,
             const float* __restrict__ gq, const float* __restrict__ beq,
             const float* __restrict__ gk, const float* __restrict__ bek,
             unsigned* __restrict__ bq_, unsigned* __restrict__ bk_,
             float* __restrict__ mursq, float* __restrict__ mursk,
             unsigned* __restrict__ flagq, unsigned* __restrict__ flagk,
             int* __restrict__ cnt)
{
    const int zz = blockIdx.y;
    const __half* X = zz ? Xk : Xq;
    const float* gamma = zz ? gk : gq;
    const float* beta  = zz ? bek : beq;
    unsigned* bits = zz ? bk_ : bq_;
    float* murs = zz ? mursk : mursq;
    unsigned* flags = zz ? flagk : flagq;
    int* cp = cnt + zz;

    const int row  = blockIdx.x;
    const int t    = threadIdx.x;
    const int lane = t & 31;
    const int wid  = t >> 5;

    const __half* xr = X + (size_t)row * D_;

    float x[4];
    float s = 0.f, sq = 0.f;
#pragma unroll
    for (int i = 0; i < 4; i++) {
        x[i] = __half2float(xr[i * 256 + t]);
        s  += x[i];
        sq += x[i] * x[i];
    }
#pragma unroll
    for (int off = 16; off > 0; off >>= 1) {
        s  += __shfl_xor_sync(0xffffffffu, s,  off);
        sq += __shfl_xor_sync(0xffffffffu, sq, off);
    }
    __shared__ float ss[8], sqq[8];
    __shared__ float s_mu, s_rs;
    if (lane == 0) { ss[wid] = s; sqq[wid] = sq; }
    __syncthreads();
    if (wid == 0) {
        float a = (lane < 8) ? ss[lane]  : 0.f;
        float b = (lane < 8) ? sqq[lane] : 0.f;
#pragma unroll
        for (int off = 4; off > 0; off >>= 1) {
            a += __shfl_xor_sync(0xffffffffu, a, off);
            b += __shfl_xor_sync(0xffffffffu, b, off);
        }
        if (lane == 0) {
            float mu  = a * (1.f / D_);
            float var = b * (1.f / D_) - mu * mu;
            s_mu = mu;
            s_rs = rsqrtf(var + EPS_);
            murs[row * 2 + 0] = mu;
            murs[row * 2 + 1] = s_rs;
        }
    }
    __syncthreads();
    const float mu = s_mu, rs = s_rs;

#pragma unroll
    for (int i = 0; i < 4; i++) {
        int d = i * 256 + t;
        float y = (x[i] - mu) * rs * gamma[d] + beta[d];
        unsigned word = __ballot_sync(0xffffffffu, y >= 2.0f);
        if (lane == 0) bits[(size_t)row * 32 + i * 8 + wid] = word;
        if (fabsf(y - 2.0f) < TAU) {
            int idx = atomicAdd(cp, 1);
            if (idx < FMAX) flags[idx] = ((unsigned)row << 10) | (unsigned)d;
        }
    }
}

// ---------------- fused exact fixup (grid.y: q/k) ----------------
#define FIX_WARPS 2048
__global__ __launch_bounds__(128)
void fixup2(const float* __restrict__ Q, const float* __restrict__ K_,
            const float* __restrict__ Wq, const float* __restrict__ Wk,
            const float* __restrict__ bq_, const float* __restrict__ bk_,
            const float* __restrict__ gq, const float* __restrict__ beq,
            const float* __restrict__ gk, const float* __restrict__ bek,
            const float* __restrict__ mursq, const float* __restrict__ mursk,
            const unsigned* __restrict__ flagq, const unsigned* __restrict__ flagk,
            const int* __restrict__ cnt,
            unsigned* __restrict__ bitsq, unsigned* __restrict__ bitsk)
{
    const int zz = blockIdx.y;
    const float* Xsrc = zz ? K_ : Q;
    const float* W = zz ? Wk : Wq;
    const float* bias = zz ? bk_ : bq_;
    const float* gamma = zz ? gk : gq;
    const float* beta = zz ? bek : beq;
    const float* murs = zz ? mursk : mursq;
    const unsigned* flags = zz ? flagk : flagq;
    unsigned* bits = zz ? bitsk : bitsq;

    const int wgid = (blockIdx.x * 128 + threadIdx.x) >> 5;
    const int lane = threadIdx.x & 31;
    int n = cnt[zz];
    if (n > FMAX) n = FMAX;

    for (int i = wgid; i < n; i += FIX_WARPS) {
        unsigned f = flags[i];
        int row = f >> 10, col = f & 1023;
        const float* xr = Xsrc + (size_t)row * D_;
        const float* wr = W + (size_t)col * D_;
        float s = 0.f;
#pragma unroll 4
        for (int k = lane; k < D_; k += 32)
            if (xr[k] >= 2.f) s += wr[k];
#pragma unroll
        for (int off = 16; off > 0; off >>= 1)
            s += __shfl_xor_sync(0xffffffffu, s, off);
        if (lane == 0) {
            float mu = murs[row * 2 + 0], rs = murs[row * 2 + 1];
            float y = (s + bias[col] - mu) * rs * gamma[col] + beta[col];
            unsigned m = 1u << (col & 31);
            unsigned* wp = &bits[(size_t)row * 32 + (col >> 5)];
            if (y >= 2.f) atomicOr(wp, m);
            else          atomicAnd(wp, ~m);
        }
    }
}

// ---------------- HMMA flash attention: double-buffered P, 1 sync/chunk ----------------
#define AT_PH   0                       // half [2][128][40]    20480
#define AT_VH   20480                   // half [2][32][72]      9216
#define AT_KB   29696                   // unsigned [1024][2]    8192
#define AT_SUM  37888                   // float [128]            512
#define AT_LUT  38400                   // float [65]             272
#define AT_SMEM (38672 + 1024)

__global__ __launch_bounds__(128, 4)
void attn_kernel(const unsigned* __restrict__ qbits, const unsigned* __restrict__ kbits,
                 const __half* __restrict__ Vh,
                 const unsigned* __restrict__ mbits,
                 __half* __restrict__ outh)
{
    extern __shared__ char raw[];
    char* sb = (char*)(((uintptr_t)raw + 1023) & ~(uintptr_t)1023);
    __half*   sPh  = (__half*)(sb + AT_PH);    // [2][128][40]
    __half*   sVh  = (__half*)(sb + AT_VH);    // [2][32][72]
    unsigned* sKb  = (unsigned*)(sb + AT_KB);  // [1024][2]
    float*    sSum = (float*)(sb + AT_SUM);
    float*    sLut = (float*)(sb + AT_LUT);

    const int qblk = blockIdx.x;
    const int h    = blockIdx.y;
    const int b    = blockIdx.z;
    const int t    = threadIdx.x;
    const int lane = t & 31;
    const int wid  = t >> 5;

    const uint2 qww = *(const uint2*)&qbits[((size_t)(b * S_ + qblk * 128 + t)) * 32 + h * 2];
    const unsigned long long q01 = ((unsigned long long)qww.y << 32) | qww.x;

    float acc[2][8][4];
#pragma unroll
    for (int i = 0; i < 2; i++)
#pragma unroll
        for (int j = 0; j < 8; j++)
#pragma unroll
            for (int r = 0; r < 4; r++) acc[i][j][r] = 0.f;
    float ssum = 0.f;

    auto loadV = [&](int c) {
        __half* dvh = sVh + (c & 1) * 32 * 72;
        const size_t gb = ((size_t)(b * S_ + c * 32)) * D_ + h * HD_;
#pragma unroll
        for (int i = 0; i < 2; i++) {
            int id = i * 128 + t;
            int r  = id >> 3, ch = id & 7;
            cpa16(smem_u32(dvh + r * 72 + ch * 8), Vh + gb + (size_t)r * D_ + ch * 8);
        }
    };

    // e-compute for chunk cc into buffer cc&1 (thread t owns q-row t)
    auto compE = [&](int cc, unsigned mwv) {
        __half* ph = sPh + (cc & 1) * 128 * 40 + t * 40;
        const int k0 = cc * 32;
        const unsigned long long* kb64 = (const unsigned long long*)sKb;
#pragma unroll
        for (int j = 0; j < 32; j += 2) {
            int s0 = __popcll(q01 & kb64[k0 + j]);
            int s1 = __popcll(q01 & kb64[k0 + j + 1]);
            float e0 = sLut[s0 * (int)((mwv >> j) & 1u)];
            float e1 = sLut[s1 * (int)((mwv >> (j + 1)) & 1u)];
            __half h0 = __float2half_rn(e0), h1 = __float2half_rn(e1);
            ssum += __half2float(h0) + __half2float(h1);
            *(unsigned*)(ph + j) = packh2(h0, h1);
        }
    };

    // preload K bits + LUT
#pragma unroll
    for (int i = 0; i < 8; i++) {
        int j = i * 128 + t;
        *(uint2*)&sKb[j * 2] = *(const uint2*)&kbits[((size_t)(b * S_ + j)) * 32 + h * 2];
    }
    if (t < 65) sLut[t] = __expf((float)t * 0.125f);

    loadV(0);
    asm volatile("cp.async.commit_group;" ::: "memory");

    const unsigned* mrow = mbits + b * 32 * S_ + qblk * 128 + t;
    unsigned mw = mrow[0];
    __syncthreads();                    // sKb/sLut visible

    compE(0, mw);
    mw = mrow[S_];                      // chunk 1 mask
    __syncthreads();                    // sPh[0] visible

    for (int c = 0; c < 32; c++) {
        if (c + 1 < 32) loadV(c + 1);
        asm volatile("cp.async.commit_group;" ::: "memory");

        // compute e(c+1) into the other P buffer (overlaps V latency + MMA issue)
        if (c + 1 < 32) {
            compE(c + 1, mw);
            mw = (c + 2 < 32) ? mrow[(size_t)(c + 2) * S_] : 0u;
        }

        asm volatile("cp.async.wait_group 1;" ::: "memory");   // V(c) ready

        // MMA: P(c)[128x32] @ V(c)[32x64]
        const __half* phb = sPh + (c & 1) * 128 * 40;
        const __half* vhb = sVh + (c & 1) * 32 * 72;
        const int lr  = lane & 15;
        const int lc8 = (lane >> 4) * 8;
        const int l8  = lane & 7;
        const int ks8 = ((lane >> 3) & 1) * 8;
        const int ns8 = (lane >> 4) * 8;
#pragma unroll
        for (int kk = 0; kk < 2; kk++) {
            unsigned ah[2][4];
#pragma unroll
            for (int mi = 0; mi < 2; mi++) {
                const int rofs = (wid * 32 + mi * 16 + lr) * 40 + kk * 16 + lc8;
                ldm4(ah[mi], phb + rofs);
            }
            unsigned vh[4][4];
#pragma unroll
            for (int nb = 0; nb < 4; nb++) {
                const int vofs = (kk * 16 + ks8 + l8) * 72 + nb * 16 + ns8;
                ldm4t(vh[nb], vhb + vofs);
            }
#pragma unroll
            for (int mi = 0; mi < 2; mi++) {
#pragma unroll
                for (int nj = 0; nj < 8; nj++) {
                    const int nb = nj >> 1, half = nj & 1;
                    mma16816(acc[mi][nj], ah[mi], vh[nb][half * 2], vh[nb][half * 2 + 1]);
                }
            }
        }
        __syncthreads();   // P(c+1) visible to all; P(c) buffer free for e(c+2)
    }

    sSum[t] = ssum;
    __syncthreads();

    const int g = lane >> 2, tg = lane & 3;
#pragma unroll
    for (int mi = 0; mi < 2; mi++) {
        const int qr0 = wid * 32 + mi * 16 + g;
        const float inv0 = 1.f / sSum[qr0];
        const float inv1 = 1.f / sSum[qr0 + 8];
        const size_t base0 = ((size_t)(b * S_ + qblk * 128 + qr0)) * D_ + h * HD_;
#pragma unroll
        for (int nj = 0; nj < 8; nj++) {
            const int n = nj * 8 + tg * 2;
            float v0 = acc[mi][nj][0] * inv0;
            float v1 = acc[mi][nj][1] * inv0;
            float v2 = acc[mi][nj][2] * inv1;
            float v3 = acc[mi][nj][3] * inv1;
            *(unsigned*)(outh + base0 + n)          = packh2(__float2half_rn(v0), __float2half_rn(v1));
            *(unsigned*)(outh + base0 + 8 * D_ + n) = packh2(__float2half_rn(v2), __float2half_rn(v3));
        }
    }
}

// ---------------- launch ----------------
extern "C" void kernel_launch(void* const* d_in, const int* in_sizes, int n_in,
                              void* d_out, int out_size)
{
    const float* Q   = (const float*)d_in[0];
    const float* K_  = (const float*)d_in[1];
    const float* adj = (const float*)d_in[2];
    const float* Wq  = (const float*)d_in[3];
    const float* bq  = (const float*)d_in[4];
    const float* Wk  = (const float*)d_in[5];
    const float* bk  = (const float*)d_in[6];
    const float* Wv  = (const float*)d_in[7];
    const float* bv  = (const float*)d_in[8];
    const float* Wo  = (const float*)d_in[9];
    const float* bo  = (const float*)d_in[10];
    const float* gq  = (const float*)d_in[11];
    const float* beq = (const float*)d_in[12];
    const float* gk  = (const float*)d_in[13];
    const float* bek = (const float*)d_in[14];
    float* out = (float*)d_out;

    float *mursq, *mursk;
    __half *Xqh, *Xkh, *Qb, *Kb, *Ath, *Vh, *Wq1, *Wk1, *Wv1, *Wo1;
    unsigned *qb, *kb, *mb, *flagq, *flagk;
    int* cnt;
    cudaGetSymbolAddress((void**)&Xqh,  g_Xqh);
    cudaGetSymbolAddress((void**)&Xkh,  g_Xkh);
    cudaGetSymbolAddress((void**)&Qb,   g_Qb);
    cudaGetSymbolAddress((void**)&Kb,   g_Kb);
    cudaGetSymbolAddress((void**)&Ath,  g_Ath);
    cudaGetSymbolAddress((void**)&Vh,   g_Vh);
    cudaGetSymbolAddress((void**)&Wq1,  g_Wq1);
    cudaGetSymbolAddress((void**)&Wk1,  g_Wk1);
    cudaGetSymbolAddress((void**)&Wv1,  g_Wv1);
    cudaGetSymbolAddress((void**)&Wo1,  g_Wo1);
    cudaGetSymbolAddress((void**)&qb,   g_qb);
    cudaGetSymbolAddress((void**)&kb,   g_kb);
    cudaGetSymbolAddress((void**)&mb,   g_mb);
    cudaGetSymbolAddress((void**)&mursq, g_mursq);
    cudaGetSymbolAddress((void**)&mursk, g_mursk);
    cudaGetSymbolAddress((void**)&flagq, g_flagq);
    cudaGetSymbolAddress((void**)&flagk, g_flagk);
    cudaGetSymbolAddress((void**)&cnt,   g_cnt);

    const int smem1 = 3 * 2 * TILEB + 1024;   // 99328 (S=3, 2 tiles)
    cudaFuncSetAttribute((const void*)gemm3,
                         cudaFuncAttributeMaxDynamicSharedMemorySize, smem1);
    cudaFuncSetAttribute((const void*)hgemm_o<3>,
                         cudaFuncAttributeMaxDynamicSharedMemorySize, smem1);
    cudaFuncSetAttribute((const void*)attn_kernel,
                         cudaFuncAttributeMaxDynamicSharedMemorySize, AT_SMEM);

    const int WELEM = D_ * D_;
    prep_w4<<<dim3(WELEM / 4 / 256, 4), 256>>>(Wq, Wk, Wv, Wo, Wq1, Wk1, Wv1, Wo1);
    prep_bin2<<<dim3(ROWS * D_ / 4 / 256, 2), 256>>>(Q, K_, Qb, Kb);
    prep_mask<<<B_ * 32 * S_ / 256, 256>>>(adj, mb, cnt);

    gemm3<<<dim3(D_ / 128, ROWS / 128, 3), 256, smem1>>>(
        Qb, Kb, Wq1, Wk1, Wv1, bq, bk, bv, Xqh, Xkh, Vh);

    ln_lif2<<<dim3(ROWS, 2), 256>>>(Xqh, Xkh, gq, beq, gk, bek,
                                    qb, kb, mursq, mursk, flagq, flagk, cnt);

    fixup2<<<dim3(FIX_WARPS / 4, 2), 128>>>(Q, K_, Wq, Wk, bq, bk,
                                            gq, beq, gk, bek, mursq, mursk,
                                            flagq, flagk, cnt, qb, kb);

    attn_kernel<<<dim3(8, H_, B_), 128, AT_SMEM>>>(qb, kb, Vh, mb, Ath);

    hgemm_o<3><<<dim3(D_ / 128, ROWS / 128), 256, smem1>>>(Ath, Wo1, bo, Ath, out);
}

// round 16
// speedup vs baseline: 1.5750x; 1.0485x over previous
#include <cuda_runtime.h>
#include <cuda_fp16.h>
#include <cstdint>

// Problem constants
#define B_   8
#define S_   1024
#define D_   1024
#define H_   16
#define HD_  64
#define ROWS (B_ * S_)
#define EPS_ 1e-5f

// fp16 GEMM tiling: K chunk 64 fp16 (= 128-byte SW128 rows)
#define BKC    64
#define TILEB  16384
#define NCH    (D_ / BKC)

// LIF borderline fixup
#define TAU    5e-3f
#define FMAX   (1 << 17)

#define SW128(x) ((x) ^ (((x) >> 3) & 0x70))

// ---------------- scratch (device globals) ----------------
__device__ __half g_Xqh[ROWS * D_];
__device__ __half g_Xkh[ROWS * D_];
__device__ __half g_Qb[ROWS * D_];
__device__ __half g_Kb[ROWS * D_];
__device__ __half g_Ath[ROWS * D_];
__device__ __half g_Vh[ROWS * D_];
__device__ __half g_Wq1[D_ * D_];
__device__ __half g_Wk1[D_ * D_];
__device__ __half g_Wv1[D_ * D_];
__device__ __half g_Wo1[D_ * D_];
__device__ unsigned g_qb[ROWS * 32];
__device__ unsigned g_kb[ROWS * 32];
__device__ unsigned g_mb[B_ * 32 * S_];   // mask bits: [b][kchunk32][q]
__device__ float    g_mursq[ROWS * 2];
__device__ float    g_mursk[ROWS * 2];
__device__ unsigned g_flagq[FMAX];
__device__ unsigned g_flagk[FMAX];
__device__ int      g_cnt[2];

// ---------------- helpers ----------------
__device__ __forceinline__ uint32_t smem_u32(const void* p) {
    return (uint32_t)__cvta_generic_to_shared(p);
}
__device__ __forceinline__ float mishf(float x) {
    float sp = (x > 20.f) ? x : log1pf(__expf(x));
    return x * tanhf(sp);
}
__device__ __forceinline__ unsigned packh2(__half a, __half b) {
    __half2 t = __halves2half2(a, b);
    return *reinterpret_cast<unsigned*>(&t);
}
__device__ __forceinline__ void ldm4(unsigned* r, const void* p) {
    unsigned addr = smem_u32(p);
    asm volatile("ldmatrix.sync.aligned.m8n8.x4.shared.b16 {%0,%1,%2,%3}, [%4];"
        : "=r"(r[0]), "=r"(r[1]), "=r"(r[2]), "=r"(r[3]) : "r"(addr));
}
__device__ __forceinline__ void ldm4t(unsigned* r, const void* p) {
    unsigned addr = smem_u32(p);
    asm volatile("ldmatrix.sync.aligned.m8n8.x4.trans.shared.b16 {%0,%1,%2,%3}, [%4];"
        : "=r"(r[0]), "=r"(r[1]), "=r"(r[2]), "=r"(r[3]) : "r"(addr));
}
__device__ __forceinline__ void mma16816(float* c, const unsigned* a, unsigned b0, unsigned b1) {
    asm volatile("mma.sync.aligned.m16n8k16.row.col.f32.f16.f16.f32 "
        "{%0,%1,%2,%3}, {%4,%5,%6,%7}, {%8,%9}, {%0,%1,%2,%3};"
        : "+f"(c[0]), "+f"(c[1]), "+f"(c[2]), "+f"(c[3])
        : "r"(a[0]), "r"(a[1]), "r"(a[2]), "r"(a[3]), "r"(b0), "r"(b1));
}
__device__ __forceinline__ void cpa16(uint32_t sa, const void* g) {
    asm volatile("cp.async.cg.shared.global [%0], [%1], 16;" :: "r"(sa), "l"(g));
}

// ---------------- fused prep kernels ----------------
__global__ __launch_bounds__(256)
void prep_w4(const float* __restrict__ Wq, const float* __restrict__ Wk,
             const float* __restrict__ Wv, const float* __restrict__ Wo,
             __half* __restrict__ Oq, __half* __restrict__ Ok,
             __half* __restrict__ Ov, __half* __restrict__ Oo)
{
    int z = blockIdx.y;
    const float* W = (z == 0) ? Wq : ((z == 1) ? Wk : ((z == 2) ? Wv : Wo));
    __half* O = (z == 0) ? Oq : ((z == 1) ? Ok : ((z == 2) ? Ov : Oo));
    int i = blockIdx.x * blockDim.x + threadIdx.x;
    float4 v = ((const float4*)W)[i];
    ((uint2*)O)[i] = make_uint2(packh2(__float2half_rn(v.x), __float2half_rn(v.y)),
                                packh2(__float2half_rn(v.z), __float2half_rn(v.w)));
}

__global__ __launch_bounds__(256)
void prep_bin2(const float* __restrict__ Xq, const float* __restrict__ Xk,
               __half* __restrict__ Yq, __half* __restrict__ Yk)
{
    const float* X = blockIdx.y ? Xk : Xq;
    __half* Y = blockIdx.y ? Yk : Yq;
    int i = blockIdx.x * blockDim.x + threadIdx.x;
    float4 v = ((const float4*)X)[i];
    ((uint2*)Y)[i] = make_uint2(
        packh2(__float2half_rn(v.x >= 2.f ? 1.f : 0.f), __float2half_rn(v.y >= 2.f ? 1.f : 0.f)),
        packh2(__float2half_rn(v.z >= 2.f ? 1.f : 0.f), __float2half_rn(v.w >= 2.f ? 1.f : 0.f)));
}

__global__ __launch_bounds__(256)
void prep_mask(const float* __restrict__ M, unsigned* __restrict__ mb, int* __restrict__ cnt)
{
    int w = blockIdx.x * blockDim.x + threadIdx.x;
    if (w < 2) cnt[w] = 0;
    int b = w >> 15;
    int c = (w >> 10) & 31;
    int q = w & 1023;
    const float4* src = (const float4*)(M + ((size_t)(b * S_ + q)) * S_ + c * 32);
    unsigned word = 0;
#pragma unroll
    for (int i = 0; i < 8; i++) {
        float4 m4 = src[i];
        word |= (m4.x != 0.f ? 1u : 0u) << (i * 4 + 0);
        word |= (m4.y != 0.f ? 1u : 0u) << (i * 4 + 1);
        word |= (m4.z != 0.f ? 1u : 0u) << (i * 4 + 2);
        word |= (m4.w != 0.f ? 1u : 0u) << (i * 4 + 3);
    }
    mb[w] = word;
}

// ---------------- fused 3-in-1 input GEMM (grid.z selects q/k/v), fp16 outputs ----------------
__global__ __launch_bounds__(256, 2)
void gemm3(const __half* __restrict__ Qb, const __half* __restrict__ Kb,
           const __half* __restrict__ Wq1, const __half* __restrict__ Wk1,
           const __half* __restrict__ Wv1,
           const float* __restrict__ bq, const float* __restrict__ bk,
           const float* __restrict__ bv,
           __half* __restrict__ Xqh, __half* __restrict__ Xkh, __half* __restrict__ Vh)
{
    constexpr int S = 3;
    extern __shared__ char raw[];
    char* base = (char*)(((uintptr_t)raw + 1023) & ~(uintptr_t)1023);

    const int z = blockIdx.z;
    const __half* A  = (z == 0) ? Qb : Kb;
    const __half* W0 = (z == 0) ? Wq1 : ((z == 1) ? Wk1 : Wv1);
    const float* bias = (z == 0) ? bq : ((z == 1) ? bk : bv);

    const int tid  = threadIdx.x;
    const int lane = tid & 31;
    const int wid  = tid >> 5;
    const int wm   = wid & 1;
    const int wn   = wid >> 1;
    const int bm   = blockIdx.y * 128;
    const int bn   = blockIdx.x * 128;

    float acc[4][4][4];
#pragma unroll
    for (int i = 0; i < 4; i++)
#pragma unroll
        for (int j = 0; j < 4; j++)
#pragma unroll
            for (int r = 0; r < 4; r++) acc[i][j][r] = 0.f;

    auto load = [&](int c) {
        char* st = base + (c % S) * 2 * TILEB;
        const int k0 = c * BKC;
#pragma unroll
        for (int t = 0; t < 2; t++) {
            const __half* src = (t == 0) ? A : W0;
            const int rb = (t == 0) ? bm : bn;
#pragma unroll
            for (int it = 0; it < 4; it++) {
                int id  = it * 256 + tid;
                int row = id >> 3;
                int ch  = id & 7;
                uint32_t sa = smem_u32(st + t * TILEB + SW128(row * 128 + ch * 16));
                cpa16(sa, src + (size_t)(rb + row) * D_ + k0 + ch * 8);
            }
        }
    };

#pragma unroll
    for (int p = 0; p < S - 1; p++) {
        load(p);
        asm volatile("cp.async.commit_group;" ::: "memory");
    }

    for (int c = 0; c < NCH; c++) {
        asm volatile("cp.async.wait_group %0;" :: "n"(S - 2) : "memory");
        __syncthreads();

        if (c + S - 1 < NCH) load(c + S - 1);
        asm volatile("cp.async.commit_group;" ::: "memory");

        const char* st  = base + (c % S) * 2 * TILEB;
        const char* tA  = st;
        const char* tW0 = st + TILEB;

        const int lr  = lane & 15;
        const int lc8 = (lane >> 4) * 8;

#pragma unroll
        for (int ks = 0; ks < 4; ks++) {
            const int cs2 = (ks * 16 + lc8) * 2;
            unsigned af[4][4];
#pragma unroll
            for (int mi = 0; mi < 4; mi++)
                ldm4(af[mi], tA + SW128((wm * 64 + mi * 16 + lr) * 128 + cs2));
            unsigned b0[2][4];
#pragma unroll
            for (int nb = 0; nb < 2; nb++)
                ldm4(b0[nb], tW0 + SW128((wn * 32 + nb * 16 + lr) * 128 + cs2));
#pragma unroll
            for (int mi = 0; mi < 4; mi++) {
#pragma unroll
                for (int nj = 0; nj < 4; nj++) {
                    const int nb = nj >> 1, sl = nj & 1;
                    mma16816(acc[mi][nj], af[mi], b0[nb][sl], b0[nb][2 + sl]);
                }
            }
        }
    }

    __half* O = (z == 0) ? Xqh : ((z == 1) ? Xkh : Vh);
    const int g = lane >> 2, tg = lane & 3;
#pragma unroll
    for (int mi = 0; mi < 4; mi++) {
#pragma unroll
        for (int nj = 0; nj < 4; nj++) {
            int m0 = bm + wm * 64 + mi * 16 + g;
            int n0 = bn + wn * 32 + nj * 8 + tg * 2;
            float2 bs = *(const float2*)(bias + n0);
            float v0 = acc[mi][nj][0] + bs.x;
            float v1 = acc[mi][nj][1] + bs.y;
            float v2 = acc[mi][nj][2] + bs.x;
            float v3 = acc[mi][nj][3] + bs.y;
            *(unsigned*)(O + (size_t)m0 * D_ + n0) =
                packh2(__float2half_rn(v0), __float2half_rn(v1));
            *(unsigned*)(O + (size_t)(m0 + 8) * D_ + n0) =
                packh2(__float2half_rn(v2), __float2half_rn(v3));
        }
    }
}

// ---------------- output GEMM (mish + fp16 residual epilogue) ----------------
template<int S>
__global__ __launch_bounds__(256, 2)
void hgemm_o(const __half* __restrict__ A, const __half* __restrict__ W0,
             const float* __restrict__ bias, const __half* __restrict__ resid,
             float* __restrict__ C)
{
    extern __shared__ char raw[];
    char* base = (char*)(((uintptr_t)raw + 1023) & ~(uintptr_t)1023);

    const int tid  = threadIdx.x;
    const int lane = tid & 31;
    const int wid  = tid >> 5;
    const int wm   = wid & 1;
    const int wn   = wid >> 1;
    const int bm   = blockIdx.y * 128;
    const int bn   = blockIdx.x * 128;

    float acc[4][4][4];
#pragma unroll
    for (int i = 0; i < 4; i++)
#pragma unroll
        for (int j = 0; j < 4; j++)
#pragma unroll
            for (int r = 0; r < 4; r++) acc[i][j][r] = 0.f;

    auto load = [&](int c) {
        char* st = base + (c % S) * 2 * TILEB;
        const int k0 = c * BKC;
#pragma unroll
        for (int t = 0; t < 2; t++) {
            const __half* src = (t == 0) ? A : W0;
            const int rb = (t == 0) ? bm : bn;
#pragma unroll
            for (int it = 0; it < 4; it++) {
                int id  = it * 256 + tid;
                int row = id >> 3;
                int ch  = id & 7;
                uint32_t sa = smem_u32(st + t * TILEB + SW128(row * 128 + ch * 16));
                cpa16(sa, src + (size_t)(rb + row) * D_ + k0 + ch * 8);
            }
        }
    };

#pragma unroll
    for (int p = 0; p < S - 1; p++) {
        load(p);
        asm volatile("cp.async.commit_group;" ::: "memory");
    }

    for (int c = 0; c < NCH; c++) {
        asm volatile("cp.async.wait_group %0;" :: "n"(S - 2) : "memory");
        __syncthreads();

        if (c + S - 1 < NCH) load(c + S - 1);
        asm volatile("cp.async.commit_group;" ::: "memory");

        const char* st  = base + (c % S) * 2 * TILEB;
        const char* tA  = st;
        const char* tW0 = st + TILEB;

        const int lr  = lane & 15;
        const int lc8 = (lane >> 4) * 8;

#pragma unroll
        for (int ks = 0; ks < 4; ks++) {
            const int cs2 = (ks * 16 + lc8) * 2;
            unsigned af[4][4];
#pragma unroll
            for (int mi = 0; mi < 4; mi++)
                ldm4(af[mi], tA + SW128((wm * 64 + mi * 16 + lr) * 128 + cs2));
            unsigned b0[2][4];
#pragma unroll
            for (int nb = 0; nb < 2; nb++)
                ldm4(b0[nb], tW0 + SW128((wn * 32 + nb * 16 + lr) * 128 + cs2));
#pragma unroll
            for (int mi = 0; mi < 4; mi++) {
#pragma unroll
                for (int nj = 0; nj < 4; nj++) {
                    const int nb = nj >> 1, sl = nj & 1;
                    mma16816(acc[mi][nj], af[mi], b0[nb][sl], b0[nb][2 + sl]);
                }
            }
        }
    }

    const int g = lane >> 2, tg = lane & 3;
#pragma unroll
    for (int mi = 0; mi < 4; mi++) {
#pragma unroll
        for (int nj = 0; nj < 4; nj++) {
            int m0 = bm + wm * 64 + mi * 16 + g;
            int n0 = bn + wn * 32 + nj * 8 + tg * 2;
            float2 bs = *(const float2*)(bias + n0);
            __half2 r0 = *(const __half2*)(resid + (size_t)m0 * D_ + n0);
            __half2 r1 = *(const __half2*)(resid + (size_t)(m0 + 8) * D_ + n0);
            float v0 = __half2float(r0.x) + mishf(acc[mi][nj][0] + bs.x);
            float v1 = __half2float(r0.y) + mishf(acc[mi][nj][1] + bs.y);
            float v2 = __half2float(r1.x) + mishf(acc[mi][nj][2] + bs.x);
            float v3 = __half2float(r1.y) + mishf(acc[mi][nj][3] + bs.y);
            *(float2*)(C + (size_t)m0 * D_ + n0)       = make_float2(v0, v1);
            *(float2*)(C + (size_t)(m0 + 8) * D_ + n0) = make_float2(v2, v3);
        }
    }
}

// ---------------- fused LayerNorm + LIF + bit-pack + flagging (fp16 X; grid.y: q/k) ----------------
__global__ __launch_bounds__(256)
void ln_lif2(const __half* __restrict__ Xq, const __half* __restrict__ Xk,
             const float* __restrict__ gq, const float* __restrict__ beq,
             const float* __restrict__ gk, const float* __restrict__ bek,
             unsigned* __restrict__ bq_, unsigned* __restrict__ bk_,
             float* __restrict__ mursq, float* __restrict__ mursk,
             unsigned* __restrict__ flagq, unsigned* __restrict__ flagk,
             int* __restrict__ cnt)
{
    const int zz = blockIdx.y;
    const __half* X = zz ? Xk : Xq;
    const float* gamma = zz ? gk : gq;
    const float* beta  = zz ? bek : beq;
    unsigned* bits = zz ? bk_ : bq_;
    float* murs = zz ? mursk : mursq;
    unsigned* flags = zz ? flagk : flagq;
    int* cp = cnt + zz;

    const int row  = blockIdx.x;
    const int t    = threadIdx.x;
    const int lane = t & 31;
    const int wid  = t >> 5;

    const __half* xr = X + (size_t)row * D_;

    float x[4];
    float s = 0.f, sq = 0.f;
#pragma unroll
    for (int i = 0; i < 4; i++) {
        x[i] = __half2float(xr[i * 256 + t]);
        s  += x[i];
        sq += x[i] * x[i];
    }
#pragma unroll
    for (int off = 16; off > 0; off >>= 1) {
        s  += __shfl_xor_sync(0xffffffffu, s,  off);
        sq += __shfl_xor_sync(0xffffffffu, sq, off);
    }
    __shared__ float ss[8], sqq[8];
    __shared__ float s_mu, s_rs;
    if (lane == 0) { ss[wid] = s; sqq[wid] = sq; }
    __syncthreads();
    if (wid == 0) {
        float a = (lane < 8) ? ss[lane]  : 0.f;
        float b = (lane < 8) ? sqq[lane] : 0.f;
#pragma unroll
        for (int off = 4; off > 0; off >>= 1) {
            a += __shfl_xor_sync(0xffffffffu, a, off);
            b += __shfl_xor_sync(0xffffffffu, b, off);
        }
        if (lane == 0) {
            float mu  = a * (1.f / D_);
            float var = b * (1.f / D_) - mu * mu;
            s_mu = mu;
            s_rs = rsqrtf(var + EPS_);
            murs[row * 2 + 0] = mu;
            murs[row * 2 + 1] = s_rs;
        }
    }
    __syncthreads();
    const float mu = s_mu, rs = s_rs;

#pragma unroll
    for (int i = 0; i < 4; i++) {
        int d = i * 256 + t;
        float y = (x[i] - mu) * rs * gamma[d] + beta[d];
        unsigned word = __ballot_sync(0xffffffffu, y >= 2.0f);
        if (lane == 0) bits[(size_t)row * 32 + i * 8 + wid] = word;
        if (fabsf(y - 2.0f) < TAU) {
            int idx = atomicAdd(cp, 1);
            if (idx < FMAX) flags[idx] = ((unsigned)row << 10) | (unsigned)d;
        }
    }
}

// ---------------- fused exact fixup (grid.y: q/k) ----------------
#define FIX_WARPS 2048
__global__ __launch_bounds__(128)
void fixup2(const float* __restrict__ Q, const float* __restrict__ K_,
            const float* __restrict__ Wq, const float* __restrict__ Wk,
            const float* __restrict__ bq_, const float* __restrict__ bk_,
            const float* __restrict__ gq, const float* __restrict__ beq,
            const float* __restrict__ gk, const float* __restrict__ bek,
            const float* __restrict__ mursq, const float* __restrict__ mursk,
            const unsigned* __restrict__ flagq, const unsigned* __restrict__ flagk,
            const int* __restrict__ cnt,
            unsigned* __restrict__ bitsq, unsigned* __restrict__ bitsk)
{
    const int zz = blockIdx.y;
    const float* Xsrc = zz ? K_ : Q;
    const float* W = zz ? Wk : Wq;
    const float* bias = zz ? bk_ : bq_;
    const float* gamma = zz ? gk : gq;
    const float* beta = zz ? bek : beq;
    const float* murs = zz ? mursk : mursq;
    const unsigned* flags = zz ? flagk : flagq;
    unsigned* bits = zz ? bitsk : bitsq;

    const int wgid = (blockIdx.x * 128 + threadIdx.x) >> 5;
    const int lane = threadIdx.x & 31;
    int n = cnt[zz];
    if (n > FMAX) n = FMAX;

    for (int i = wgid; i < n; i += FIX_WARPS) {
        unsigned f = flags[i];
        int row = f >> 10, col = f & 1023;
        const float* xr = Xsrc + (size_t)row * D_;
        const float* wr = W + (size_t)col * D_;
        float s = 0.f;
#pragma unroll 4
        for (int k = lane; k < D_; k += 32)
            if (xr[k] >= 2.f) s += wr[k];
#pragma unroll
        for (int off = 16; off > 0; off >>= 1)
            s += __shfl_xor_sync(0xffffffffu, s, off);
        if (lane == 0) {
            float mu = murs[row * 2 + 0], rs = murs[row * 2 + 1];
            float y = (s + bias[col] - mu) * rs * gamma[col] + beta[col];
            unsigned m = 1u << (col & 31);
            unsigned* wp = &bits[(size_t)row * 32 + (col >> 5)];
            if (y >= 2.f) atomicOr(wp, m);
            else          atomicAnd(wp, ~m);
        }
    }
}

// ---------------- HMMA flash attention: K-chunk 64, 16 iterations ----------------
#define AT_PH   0                       // half [128][72]       18432
#define AT_VH   18432                   // half [2][64][72]     18432
#define AT_KB   36864                   // unsigned [1024][2]    8192
#define AT_SUM  45056                   // float [128]            512
#define AT_LUT  45568                   // float [65]             272
#define AT_SMEM (45840 + 1024)

__global__ __launch_bounds__(128, 4)
void attn_kernel(const unsigned* __restrict__ qbits, const unsigned* __restrict__ kbits,
                 const __half* __restrict__ Vh,
                 const unsigned* __restrict__ mbits,
                 __half* __restrict__ outh)
{
    extern __shared__ char raw[];
    char* sb = (char*)(((uintptr_t)raw + 1023) & ~(uintptr_t)1023);
    __half*   sPh  = (__half*)(sb + AT_PH);    // [128][72]
    __half*   sVh  = (__half*)(sb + AT_VH);    // [2][64][72]
    unsigned* sKb  = (unsigned*)(sb + AT_KB);  // [1024][2]
    float*    sSum = (float*)(sb + AT_SUM);
    float*    sLut = (float*)(sb + AT_LUT);

    const int qblk = blockIdx.x;
    const int h    = blockIdx.y;
    const int b    = blockIdx.z;
    const int t    = threadIdx.x;
    const int lane = t & 31;
    const int wid  = t >> 5;

    const uint2 qww = *(const uint2*)&qbits[((size_t)(b * S_ + qblk * 128 + t)) * 32 + h * 2];
    const unsigned long long q01 = ((unsigned long long)qww.y << 32) | qww.x;

    float acc[2][8][4];
#pragma unroll
    for (int i = 0; i < 2; i++)
#pragma unroll
        for (int j = 0; j < 8; j++)
#pragma unroll
            for (int r = 0; r < 4; r++) acc[i][j][r] = 0.f;
    float ssum = 0.f;

    // load 64 V rows (8 KB) for chunk c into buffer c&1
    auto loadV = [&](int c) {
        __half* dvh = sVh + (c & 1) * 64 * 72;
        const size_t gb = ((size_t)(b * S_ + c * 64)) * D_ + h * HD_;
#pragma unroll
        for (int i = 0; i < 4; i++) {
            int id = i * 128 + t;
            int r  = id >> 3, ch = id & 7;
            cpa16(smem_u32(dvh + r * 72 + ch * 8), Vh + gb + (size_t)r * D_ + ch * 8);
        }
    };

    // preload K bits + LUT
#pragma unroll
    for (int i = 0; i < 8; i++) {
        int j = i * 128 + t;
        *(uint2*)&sKb[j * 2] = *(const uint2*)&kbits[((size_t)(b * S_ + j)) * 32 + h * 2];
    }
    if (t < 65) sLut[t] = __expf((float)t * 0.125f);

    loadV(0);
    asm volatile("cp.async.commit_group;" ::: "memory");

    const unsigned* mrow = mbits + b * 32 * S_ + qblk * 128 + t;
    unsigned mw0 = mrow[0];
    unsigned mw1 = mrow[S_];
    __syncthreads();   // sKb/sLut visible

    for (int c = 0; c < 16; c++) {
        const int k0 = c * 64;

        if (c + 1 < 16) loadV(c + 1);
        asm volatile("cp.async.commit_group;" ::: "memory");
        unsigned mn0 = 0u, mn1 = 0u;
        if (c + 1 < 16) {
            mn0 = mrow[(size_t)(2 * c + 2) * S_];
            mn1 = mrow[(size_t)(2 * c + 3) * S_];
        }

        // e-compute: thread t owns q-row t; 64 columns
        {
            __half* ph = sPh + t * 72;
            const unsigned long long* kb64 = (const unsigned long long*)sKb;
#pragma unroll
            for (int j = 0; j < 64; j += 2) {
                const unsigned mwv = (j < 32) ? mw0 : mw1;
                const int jj = j & 31;
                int s0 = __popcll(q01 & kb64[k0 + j]);
                int s1 = __popcll(q01 & kb64[k0 + j + 1]);
                float e0 = sLut[s0 * (int)((mwv >> jj) & 1u)];
                float e1 = sLut[s1 * (int)((mwv >> (jj + 1)) & 1u)];
                __half h0 = __float2half_rn(e0), h1 = __float2half_rn(e1);
                ssum += __half2float(h0) + __half2float(h1);
                *(unsigned*)(ph + j) = packh2(h0, h1);
            }
        }
        mw0 = mn0; mw1 = mn1;
        __syncthreads();   // sPh visible
        asm volatile("cp.async.wait_group 1;" ::: "memory");   // V(c) ready

        // MMA: P[128x64] @ V[64x64]
        const __half* vhb = sVh + (c & 1) * 64 * 72;
        const int lr  = lane & 15;
        const int lc8 = (lane >> 4) * 8;
        const int l8  = lane & 7;
        const int ks8 = ((lane >> 3) & 1) * 8;
        const int ns8 = (lane >> 4) * 8;
#pragma unroll
        for (int kk = 0; kk < 4; kk++) {
            unsigned ah[2][4];
#pragma unroll
            for (int mi = 0; mi < 2; mi++) {
                const int rofs = (wid * 32 + mi * 16 + lr) * 72 + kk * 16 + lc8;
                ldm4(ah[mi], sPh + rofs);
            }
            unsigned vh[4][4];
#pragma unroll
            for (int nb = 0; nb < 4; nb++) {
                const int vofs = (kk * 16 + ks8 + l8) * 72 + nb * 16 + ns8;
                ldm4t(vh[nb], vhb + vofs);
            }
#pragma unroll
            for (int mi = 0; mi < 2; mi++) {
#pragma unroll
                for (int nj = 0; nj < 8; nj++) {
                    const int nb = nj >> 1, half = nj & 1;
                    mma16816(acc[mi][nj], ah[mi], vh[nb][half * 2], vh[nb][half * 2 + 1]);
                }
            }
        }
        __syncthreads();   // MMA done; sPh reusable next iter
    }

    sSum[t] = ssum;
    __syncthreads();

    const int g = lane >> 2, tg = lane & 3;
#pragma unroll
    for (int mi = 0; mi < 2; mi++) {
        const int qr0 = wid * 32 + mi * 16 + g;
        const float inv0 = 1.f / sSum[qr0];
        const float inv1 = 1.f / sSum[qr0 + 8];
        const size_t base0 = ((size_t)(b * S_ + qblk * 128 + qr0)) * D_ + h * HD_;
#pragma unroll
        for (int nj = 0; nj < 8; nj++) {
            const int n = nj * 8 + tg * 2;
            float v0 = acc[mi][nj][0] * inv0;
            float v1 = acc[mi][nj][1] * inv0;
            float v2 = acc[mi][nj][2] * inv1;
            float v3 = acc[mi][nj][3] * inv1;
            *(unsigned*)(outh + base0 + n)          = packh2(__float2half_rn(v0), __float2half_rn(v1));
            *(unsigned*)(outh + base0 + 8 * D_ + n) = packh2(__float2half_rn(v2), __float2half_rn(v3));
        }
    }
}

// ---------------- launch ----------------
extern "C" void kernel_launch(void* const* d_in, const int* in_sizes, int n_in,
                              void* d_out, int out_size)
{
    const float* Q   = (const float*)d_in[0];
    const float* K_  = (const float*)d_in[1];
    const float* adj = (const float*)d_in[2];
    const float* Wq  = (const float*)d_in[3];
    const float* bq  = (const float*)d_in[4];
    const float* Wk  = (const float*)d_in[5];
    const float* bk  = (const float*)d_in[6];
    const float* Wv  = (const float*)d_in[7];
    const float* bv  = (const float*)d_in[8];
    const float* Wo  = (const float*)d_in[9];
    const float* bo  = (const float*)d_in[10];
    const float* gq  = (const float*)d_in[11];
    const float* beq = (const float*)d_in[12];
    const float* gk  = (const float*)d_in[13];
    const float* bek = (const float*)d_in[14];
    float* out = (float*)d_out;

    float *mursq, *mursk;
    __half *Xqh, *Xkh, *Qb, *Kb, *Ath, *Vh, *Wq1, *Wk1, *Wv1, *Wo1;
    unsigned *qb, *kb, *mb, *flagq, *flagk;
    int* cnt;
    cudaGetSymbolAddress((void**)&Xqh,  g_Xqh);
    cudaGetSymbolAddress((void**)&Xkh,  g_Xkh);
    cudaGetSymbolAddress((void**)&Qb,   g_Qb);
    cudaGetSymbolAddress((void**)&Kb,   g_Kb);
    cudaGetSymbolAddress((void**)&Ath,  g_Ath);
    cudaGetSymbolAddress((void**)&Vh,   g_Vh);
    cudaGetSymbolAddress((void**)&Wq1,  g_Wq1);
    cudaGetSymbolAddress((void**)&Wk1,  g_Wk1);
    cudaGetSymbolAddress((void**)&Wv1,  g_Wv1);
    cudaGetSymbolAddress((void**)&Wo1,  g_Wo1);
    cudaGetSymbolAddress((void**)&qb,   g_qb);
    cudaGetSymbolAddress((void**)&kb,   g_kb);
    cudaGetSymbolAddress((void**)&mb,   g_mb);
    cudaGetSymbolAddress((void**)&mursq, g_mursq);
    cudaGetSymbolAddress((void**)&mursk, g_mursk);
    cudaGetSymbolAddress((void**)&flagq, g_flagq);
    cudaGetSymbolAddress((void**)&flagk, g_flagk);
    cudaGetSymbolAddress((void**)&cnt,   g_cnt);

    const int smem1 = 3 * 2 * TILEB + 1024;   // 99328 (S=3, 2 tiles)
    cudaFuncSetAttribute((const void*)gemm3,
                         cudaFuncAttributeMaxDynamicSharedMemorySize, smem1);
    cudaFuncSetAttribute((const void*)hgemm_o<3>,
                         cudaFuncAttributeMaxDynamicSharedMemorySize, smem1);
    cudaFuncSetAttribute((const void*)attn_kernel,
                         cudaFuncAttributeMaxDynamicSharedMemorySize, AT_SMEM);

    const int WELEM = D_ * D_;
    prep_w4<<<dim3(WELEM / 4 / 256, 4), 256>>>(Wq, Wk, Wv, Wo, Wq1, Wk1, Wv1, Wo1);
    prep_bin2<<<dim3(ROWS * D_ / 4 / 256, 2), 256>>>(Q, K_, Qb, Kb);
    prep_mask<<<B_ * 32 * S_ / 256, 256>>>(adj, mb, cnt);

    gemm3<<<dim3(D_ / 128, ROWS / 128, 3), 256, smem1>>>(
        Qb, Kb, Wq1, Wk1, Wv1, bq, bk, bv, Xqh, Xkh, Vh);

    ln_lif2<<<dim3(ROWS, 2), 256>>>(Xqh, Xkh, gq, beq, gk, bek,
                                    qb, kb, mursq, mursk, flagq, flagk, cnt);

    fixup2<<<dim3(FIX_WARPS / 4, 2), 128>>>(Q, K_, Wq, Wk, bq, bk,
                                            gq, beq, gk, bek, mursq, mursk,
                                            flagq, flagk, cnt, qb, kb);

    attn_kernel<<<dim3(8, H_, B_), 128, AT_SMEM>>>(qb, kb, Vh, mb, Ath);

    hgemm_o<3><<<dim3(D_ / 128, ROWS / 128), 256, smem1>>>(Ath, Wo1, bo, Ath, out);
}

// round 17
// speedup vs baseline: 1.6522x; 1.0491x over previous
#include <cuda_runtime.h>
#include <cuda_fp16.h>
#include <cstdint>

// Problem constants
#define B_   8
#define S_   1024
#define D_   1024
#define H_   16
#define HD_  64
#define ROWS (B_ * S_)
#define EPS_ 1e-5f

// fp16 GEMM tiling: K chunk 64 fp16 (= 128-byte SW128 rows)
#define BKC    64
#define TILEB  16384
#define NCH    (D_ / BKC)

// LIF borderline fixup
#define TAU    5e-3f
#define FMAX   (1 << 17)

#define SW128(x) ((x) ^ (((x) >> 3) & 0x70))

// ---------------- scratch (device globals) ----------------
__device__ __half g_Xqh[ROWS * D_];
__device__ __half g_Xkh[ROWS * D_];
__device__ __half g_Qb[ROWS * D_];
__device__ __half g_Kb[ROWS * D_];
__device__ __half g_Ath[ROWS * D_];
__device__ __half g_Vh[ROWS * D_];
__device__ __half g_Wq1[D_ * D_];
__device__ __half g_Wk1[D_ * D_];
__device__ __half g_Wv1[D_ * D_];
__device__ __half g_Wo1[D_ * D_];
__device__ unsigned g_qb[ROWS * 32];
__device__ unsigned g_kb[ROWS * 32];
__device__ unsigned g_mb[B_ * 32 * S_];   // mask bits: [b][kchunk32][q]
__device__ float    g_mursq[ROWS * 2];
__device__ float    g_mursk[ROWS * 2];
__device__ unsigned g_flagq[FMAX];
__device__ unsigned g_flagk[FMAX];
__device__ int      g_cnt[2];

// ---------------- helpers ----------------
__device__ __forceinline__ uint32_t smem_u32(const void* p) {
    return (uint32_t)__cvta_generic_to_shared(p);
}
__device__ __forceinline__ float mishf(float x) {
    float sp = (x > 20.f) ? x : log1pf(__expf(x));
    return x * tanhf(sp);
}
__device__ __forceinline__ unsigned packh2(__half a, __half b) {
    __half2 t = __halves2half2(a, b);
    return *reinterpret_cast<unsigned*>(&t);
}
__device__ __forceinline__ void ldm4(unsigned* r, const void* p) {
    unsigned addr = smem_u32(p);
    asm volatile("ldmatrix.sync.aligned.m8n8.x4.shared.b16 {%0,%1,%2,%3}, [%4];"
        : "=r"(r[0]), "=r"(r[1]), "=r"(r[2]), "=r"(r[3]) : "r"(addr));
}
__device__ __forceinline__ void ldm4t(unsigned* r, const void* p) {
    unsigned addr = smem_u32(p);
    asm volatile("ldmatrix.sync.aligned.m8n8.x4.trans.shared.b16 {%0,%1,%2,%3}, [%4];"
        : "=r"(r[0]), "=r"(r[1]), "=r"(r[2]), "=r"(r[3]) : "r"(addr));
}
__device__ __forceinline__ void mma16816(float* c, const unsigned* a, unsigned b0, unsigned b1) {
    asm volatile("mma.sync.aligned.m16n8k16.row.col.f32.f16.f16.f32 "
        "{%0,%1,%2,%3}, {%4,%5,%6,%7}, {%8,%9}, {%0,%1,%2,%3};"
        : "+f"(c[0]), "+f"(c[1]), "+f"(c[2]), "+f"(c[3])
        : "r"(a[0]), "r"(a[1]), "r"(a[2]), "r"(a[3]), "r"(b0), "r"(b1));
}
__device__ __forceinline__ void cpa16(uint32_t sa, const void* g) {
    asm volatile("cp.async.cg.shared.global [%0], [%1], 16;" :: "r"(sa), "l"(g));
}

// ---------------- fused prep kernels ----------------
__global__ __launch_bounds__(256)
void prep_w4(const float* __restrict__ Wq, const float* __restrict__ Wk,
             const float* __restrict__ Wv, const float* __restrict__ Wo,
             __half* __restrict__ Oq, __half* __restrict__ Ok,
             __half* __restrict__ Ov, __half* __restrict__ Oo)
{
    int z = blockIdx.y;
    const float* W = (z == 0) ? Wq : ((z == 1) ? Wk : ((z == 2) ? Wv : Wo));
    __half* O = (z == 0) ? Oq : ((z == 1) ? Ok : ((z == 2) ? Ov : Oo));
    int i = blockIdx.x * blockDim.x + threadIdx.x;
    float4 v = ((const float4*)W)[i];
    ((uint2*)O)[i] = make_uint2(packh2(__float2half_rn(v.x), __float2half_rn(v.y)),
                                packh2(__float2half_rn(v.z), __float2half_rn(v.w)));
}

__global__ __launch_bounds__(256)
void prep_bin2(const float* __restrict__ Xq, const float* __restrict__ Xk,
               __half* __restrict__ Yq, __half* __restrict__ Yk,
               int* __restrict__ cnt)
{
    const float* X = blockIdx.y ? Xk : Xq;
    __half* Y = blockIdx.y ? Yk : Yq;
    int i = blockIdx.x * blockDim.x + threadIdx.x;
    if (blockIdx.y == 0 && i < 2) cnt[i] = 0;
    float4 v = ((const float4*)X)[i];
    ((uint2*)Y)[i] = make_uint2(
        packh2(__float2half_rn(v.x >= 2.f ? 1.f : 0.f), __float2half_rn(v.y >= 2.f ? 1.f : 0.f)),
        packh2(__float2half_rn(v.z >= 2.f ? 1.f : 0.f), __float2half_rn(v.w >= 2.f ? 1.f : 0.f)));
}

__global__ __launch_bounds__(256)
void prep_mask(const float* __restrict__ M, unsigned* __restrict__ mb)
{
    int w = blockIdx.x * blockDim.x + threadIdx.x;
    int b = w >> 15;
    int c = (w >> 10) & 31;
    int q = w & 1023;
    const float4* src = (const float4*)(M + ((size_t)(b * S_ + q)) * S_ + c * 32);
    unsigned word = 0;
#pragma unroll
    for (int i = 0; i < 8; i++) {
        float4 m4 = src[i];
        word |= (m4.x != 0.f ? 1u : 0u) << (i * 4 + 0);
        word |= (m4.y != 0.f ? 1u : 0u) << (i * 4 + 1);
        word |= (m4.z != 0.f ? 1u : 0u) << (i * 4 + 2);
        word |= (m4.w != 0.f ? 1u : 0u) << (i * 4 + 3);
    }
    mb[w] = word;
}

// ---------------- input GEMM (grid.z + zofs selects q/k/v), fp16 outputs ----------------
__global__ __launch_bounds__(256, 2)
void gemm3(const __half* __restrict__ Qb, const __half* __restrict__ Kb,
           const __half* __restrict__ Wq1, const __half* __restrict__ Wk1,
           const __half* __restrict__ Wv1,
           const float* __restrict__ bq, const float* __restrict__ bk,
           const float* __restrict__ bv,
           __half* __restrict__ Xqh, __half* __restrict__ Xkh, __half* __restrict__ Vh,
           int zofs)
{
    constexpr int S = 3;
    extern __shared__ char raw[];
    char* base = (char*)(((uintptr_t)raw + 1023) & ~(uintptr_t)1023);

    const int z = blockIdx.z + zofs;
    const __half* A  = (z == 0) ? Qb : Kb;
    const __half* W0 = (z == 0) ? Wq1 : ((z == 1) ? Wk1 : Wv1);
    const float* bias = (z == 0) ? bq : ((z == 1) ? bk : bv);

    const int tid  = threadIdx.x;
    const int lane = tid & 31;
    const int wid  = tid >> 5;
    const int wm   = wid & 1;
    const int wn   = wid >> 1;
    const int bm   = blockIdx.y * 128;
    const int bn   = blockIdx.x * 128;

    float acc[4][4][4];
#pragma unroll
    for (int i = 0; i < 4; i++)
#pragma unroll
        for (int j = 0; j < 4; j++)
#pragma unroll
            for (int r = 0; r < 4; r++) acc[i][j][r] = 0.f;

    auto load = [&](int c) {
        char* st = base + (c % S) * 2 * TILEB;
        const int k0 = c * BKC;
#pragma unroll
        for (int t = 0; t < 2; t++) {
            const __half* src = (t == 0) ? A : W0;
            const int rb = (t == 0) ? bm : bn;
#pragma unroll
            for (int it = 0; it < 4; it++) {
                int id  = it * 256 + tid;
                int row = id >> 3;
                int ch  = id & 7;
                uint32_t sa = smem_u32(st + t * TILEB + SW128(row * 128 + ch * 16));
                cpa16(sa, src + (size_t)(rb + row) * D_ + k0 + ch * 8);
            }
        }
    };

#pragma unroll
    for (int p = 0; p < S - 1; p++) {
        load(p);
        asm volatile("cp.async.commit_group;" ::: "memory");
    }

    for (int c = 0; c < NCH; c++) {
        asm volatile("cp.async.wait_group %0;" :: "n"(S - 2) : "memory");
        __syncthreads();

        if (c + S - 1 < NCH) load(c + S - 1);
        asm volatile("cp.async.commit_group;" ::: "memory");

        const char* st  = base + (c % S) * 2 * TILEB;
        const char* tA  = st;
        const char* tW0 = st + TILEB;

        const int lr  = lane & 15;
        const int lc8 = (lane >> 4) * 8;

#pragma unroll
        for (int ks = 0; ks < 4; ks++) {
            const int cs2 = (ks * 16 + lc8) * 2;
            unsigned af[4][4];
#pragma unroll
            for (int mi = 0; mi < 4; mi++)
                ldm4(af[mi], tA + SW128((wm * 64 + mi * 16 + lr) * 128 + cs2));
            unsigned b0[2][4];
#pragma unroll
            for (int nb = 0; nb < 2; nb++)
                ldm4(b0[nb], tW0 + SW128((wn * 32 + nb * 16 + lr) * 128 + cs2));
#pragma unroll
            for (int mi = 0; mi < 4; mi++) {
#pragma unroll
                for (int nj = 0; nj < 4; nj++) {
                    const int nb = nj >> 1, sl = nj & 1;
                    mma16816(acc[mi][nj], af[mi], b0[nb][sl], b0[nb][2 + sl]);
                }
            }
        }
    }

    __half* O = (z == 0) ? Xqh : ((z == 1) ? Xkh : Vh);
    const int g = lane >> 2, tg = lane & 3;
#pragma unroll
    for (int mi = 0; mi < 4; mi++) {
#pragma unroll
        for (int nj = 0; nj < 4; nj++) {
            int m0 = bm + wm * 64 + mi * 16 + g;
            int n0 = bn + wn * 32 + nj * 8 + tg * 2;
            float2 bs = *(const float2*)(bias + n0);
            float v0 = acc[mi][nj][0] + bs.x;
            float v1 = acc[mi][nj][1] + bs.y;
            float v2 = acc[mi][nj][2] + bs.x;
            float v3 = acc[mi][nj][3] + bs.y;
            *(unsigned*)(O + (size_t)m0 * D_ + n0) =
                packh2(__float2half_rn(v0), __float2half_rn(v1));
            *(unsigned*)(O + (size_t)(m0 + 8) * D_ + n0) =
                packh2(__float2half_rn(v2), __float2half_rn(v3));
        }
    }
}

// ---------------- output GEMM (mish + fp16 residual epilogue) ----------------
template<int S>
__global__ __launch_bounds__(256, 2)
void hgemm_o(const __half* __restrict__ A, const __half* __restrict__ W0,
             const float* __restrict__ bias, const __half* __restrict__ resid,
             float* __restrict__ C)
{
    extern __shared__ char raw[];
    char* base = (char*)(((uintptr_t)raw + 1023) & ~(uintptr_t)1023);

    const int tid  = threadIdx.x;
    const int lane = tid & 31;
    const int wid  = tid >> 5;
    const int wm   = wid & 1;
    const int wn   = wid >> 1;
    const int bm   = blockIdx.y * 128;
    const int bn   = blockIdx.x * 128;

    float acc[4][4][4];
#pragma unroll
    for (int i = 0; i < 4; i++)
#pragma unroll
        for (int j = 0; j < 4; j++)
#pragma unroll
            for (int r = 0; r < 4; r++) acc[i][j][r] = 0.f;

    auto load = [&](int c) {
        char* st = base + (c % S) * 2 * TILEB;
        const int k0 = c * BKC;
#pragma unroll
        for (int t = 0; t < 2; t++) {
            const __half* src = (t == 0) ? A : W0;
            const int rb = (t == 0) ? bm : bn;
#pragma unroll
            for (int it = 0; it < 4; it++) {
                int id  = it * 256 + tid;
                int row = id >> 3;
                int ch  = id & 7;
                uint32_t sa = smem_u32(st + t * TILEB + SW128(row * 128 + ch * 16));
                cpa16(sa, src + (size_t)(rb + row) * D_ + k0 + ch * 8);
            }
        }
    };

#pragma unroll
    for (int p = 0; p < S - 1; p++) {
        load(p);
        asm volatile("cp.async.commit_group;" ::: "memory");
    }

    for (int c = 0; c < NCH; c++) {
        asm volatile("cp.async.wait_group %0;" :: "n"(S - 2) : "memory");
        __syncthreads();

        if (c + S - 1 < NCH) load(c + S - 1);
        asm volatile("cp.async.commit_group;" ::: "memory");

        const char* st  = base + (c % S) * 2 * TILEB;
        const char* tA  = st;
        const char* tW0 = st + TILEB;

        const int lr  = lane & 15;
        const int lc8 = (lane >> 4) * 8;

#pragma unroll
        for (int ks = 0; ks < 4; ks++) {
            const int cs2 = (ks * 16 + lc8) * 2;
            unsigned af[4][4];
#pragma unroll
            for (int mi = 0; mi < 4; mi++)
                ldm4(af[mi], tA + SW128((wm * 64 + mi * 16 + lr) * 128 + cs2));
            unsigned b0[2][4];
#pragma unroll
            for (int nb = 0; nb < 2; nb++)
                ldm4(b0[nb], tW0 + SW128((wn * 32 + nb * 16 + lr) * 128 + cs2));
#pragma unroll
            for (int mi = 0; mi < 4; mi++) {
#pragma unroll
                for (int nj = 0; nj < 4; nj++) {
                    const int nb = nj >> 1, sl = nj & 1;
                    mma16816(acc[mi][nj], af[mi], b0[nb][sl], b0[nb][2 + sl]);
                }
            }
        }
    }

    const int g = lane >> 2, tg = lane & 3;
#pragma unroll
    for (int mi = 0; mi < 4; mi++) {
#pragma unroll
        for (int nj = 0; nj < 4; nj++) {
            int m0 = bm + wm * 64 + mi * 16 + g;
            int n0 = bn + wn * 32 + nj * 8 + tg * 2;
            float2 bs = *(const float2*)(bias + n0);
            __half2 r0 = *(const __half2*)(resid + (size_t)m0 * D_ + n0);
            __half2 r1 = *(const __half2*)(resid + (size_t)(m0 + 8) * D_ + n0);
            float v0 = __half2float(r0.x) + mishf(acc[mi][nj][0] + bs.x);
            float v1 = __half2float(r0.y) + mishf(acc[mi][nj][1] + bs.y);
            float v2 = __half2float(r1.x) + mishf(acc[mi][nj][2] + bs.x);
            float v3 = __half2float(r1.y) + mishf(acc[mi][nj][3] + bs.y);
            *(float2*)(C + (size_t)m0 * D_ + n0)       = make_float2(v0, v1);
            *(float2*)(C + (size_t)(m0 + 8) * D_ + n0) = make_float2(v2, v3);
        }
    }
}

// ---------------- fused LayerNorm + LIF + bit-pack + flagging (fp16 X; grid.y: q/k) ----------------
__global__ __launch_bounds__(256)
void ln_lif2(const __half* __restrict__ Xq, const __half* __restrict__ Xk,
             const float* __restrict__ gq, const float* __restrict__ beq,
             const float* __restrict__ gk, const float* __restrict__ bek,
             unsigned* __restrict__ bq_, unsigned* __restrict__ bk_,
             float* __restrict__ mursq, float* __restrict__ mursk,
             unsigned* __restrict__ flagq, unsigned* __restrict__ flagk,
             int* __restrict__ cnt)
{
    const int zz = blockIdx.y;
    const __half* X = zz ? Xk : Xq;
    const float* gamma = zz ? gk : gq;
    const float* beta  = zz ? bek : beq;
    unsigned* bits = zz ? bk_ : bq_;
    float* murs = zz ? mursk : mursq;
    unsigned* flags = zz ? flagk : flagq;
    int* cp = cnt + zz;

    const int row  = blockIdx.x;
    const int t    = threadIdx.x;
    const int lane = t & 31;
    const int wid  = t >> 5;

    const __half* xr = X + (size_t)row * D_;

    float x[4];
    float s = 0.f, sq = 0.f;
#pragma unroll
    for (int i = 0; i < 4; i++) {
        x[i] = __half2float(xr[i * 256 + t]);
        s  += x[i];
        sq += x[i] * x[i];
    }
#pragma unroll
    for (int off = 16; off > 0; off >>= 1) {
        s  += __shfl_xor_sync(0xffffffffu, s,  off);
        sq += __shfl_xor_sync(0xffffffffu, sq, off);
    }
    __shared__ float ss[8], sqq[8];
    __shared__ float s_mu, s_rs;
    if (lane == 0) { ss[wid] = s; sqq[wid] = sq; }
    __syncthreads();
    if (wid == 0) {
        float a = (lane < 8) ? ss[lane]  : 0.f;
        float b = (lane < 8) ? sqq[lane] : 0.f;
#pragma unroll
        for (int off = 4; off > 0; off >>= 1) {
            a += __shfl_xor_sync(0xffffffffu, a, off);
            b += __shfl_xor_sync(0xffffffffu, b, off);
        }
        if (lane == 0) {
            float mu  = a * (1.f / D_);
            float var = b * (1.f / D_) - mu * mu;
            s_mu = mu;
            s_rs = rsqrtf(var + EPS_);
            murs[row * 2 + 0] = mu;
            murs[row * 2 + 1] = s_rs;
        }
    }
    __syncthreads();
    const float mu = s_mu, rs = s_rs;

#pragma unroll
    for (int i = 0; i < 4; i++) {
        int d = i * 256 + t;
        float y = (x[i] - mu) * rs * gamma[d] + beta[d];
        unsigned word = __ballot_sync(0xffffffffu, y >= 2.0f);
        if (lane == 0) bits[(size_t)row * 32 + i * 8 + wid] = word;
        if (fabsf(y - 2.0f) < TAU) {
            int idx = atomicAdd(cp, 1);
            if (idx < FMAX) flags[idx] = ((unsigned)row << 10) | (unsigned)d;
        }
    }
}

// ---------------- fused exact fixup (grid.y: q/k) ----------------
#define FIX_WARPS 2048
__global__ __launch_bounds__(128)
void fixup2(const float* __restrict__ Q, const float* __restrict__ K_,
            const float* __restrict__ Wq, const float* __restrict__ Wk,
            const float* __restrict__ bq_, const float* __restrict__ bk_,
            const float* __restrict__ gq, const float* __restrict__ beq,
            const float* __restrict__ gk, const float* __restrict__ bek,
            const float* __restrict__ mursq, const float* __restrict__ mursk,
            const unsigned* __restrict__ flagq, const unsigned* __restrict__ flagk,
            const int* __restrict__ cnt,
            unsigned* __restrict__ bitsq, unsigned* __restrict__ bitsk)
{
    const int zz = blockIdx.y;
    const float* Xsrc = zz ? K_ : Q;
    const float* W = zz ? Wk : Wq;
    const float* bias = zz ? bk_ : bq_;
    const float* gamma = zz ? gk : gq;
    const float* beta = zz ? bek : beq;
    const float* murs = zz ? mursk : mursq;
    const unsigned* flags = zz ? flagk : flagq;
    unsigned* bits = zz ? bitsk : bitsq;

    const int wgid = (blockIdx.x * 128 + threadIdx.x) >> 5;
    const int lane = threadIdx.x & 31;
    int n = cnt[zz];
    if (n > FMAX) n = FMAX;

    for (int i = wgid; i < n; i += FIX_WARPS) {
        unsigned f = flags[i];
        int row = f >> 10, col = f & 1023;
        const float* xr = Xsrc + (size_t)row * D_;
        const float* wr = W + (size_t)col * D_;
        float s = 0.f;
#pragma unroll 4
        for (int k = lane; k < D_; k += 32)
            if (xr[k] >= 2.f) s += wr[k];
#pragma unroll
        for (int off = 16; off > 0; off >>= 1)
            s += __shfl_xor_sync(0xffffffffu, s, off);
        if (lane == 0) {
            float mu = murs[row * 2 + 0], rs = murs[row * 2 + 1];
            float y = (s + bias[col] - mu) * rs * gamma[col] + beta[col];
            unsigned m = 1u << (col & 31);
            unsigned* wp = &bits[(size_t)row * 32 + (col >> 5)];
            if (y >= 2.f) atomicOr(wp, m);
            else          atomicAnd(wp, ~m);
        }
    }
}

// ---------------- HMMA flash attention: K-chunk 64, 16 iterations ----------------
#define AT_PH   0                       // half [128][72]       18432
#define AT_VH   18432                   // half [2][64][72]     18432
#define AT_KB   36864                   // unsigned [1024][2]    8192
#define AT_SUM  45056                   // float [128]            512
#define AT_LUT  45568                   // float [65]             272
#define AT_SMEM (45840 + 1024)

__global__ __launch_bounds__(128, 4)
void attn_kernel(const unsigned* __restrict__ qbits, const unsigned* __restrict__ kbits,
                 const __half* __restrict__ Vh,
                 const unsigned* __restrict__ mbits,
                 __half* __restrict__ outh)
{
    extern __shared__ char raw[];
    char* sb = (char*)(((uintptr_t)raw + 1023) & ~(uintptr_t)1023);
    __half*   sPh  = (__half*)(sb + AT_PH);    // [128][72]
    __half*   sVh  = (__half*)(sb + AT_VH);    // [2][64][72]
    unsigned* sKb  = (unsigned*)(sb + AT_KB);  // [1024][2]
    float*    sSum = (float*)(sb + AT_SUM);
    float*    sLut = (float*)(sb + AT_LUT);

    const int qblk = blockIdx.x;
    const int h    = blockIdx.y;
    const int b    = blockIdx.z;
    const int t    = threadIdx.x;
    const int lane = t & 31;
    const int wid  = t >> 5;

    const uint2 qww = *(const uint2*)&qbits[((size_t)(b * S_ + qblk * 128 + t)) * 32 + h * 2];
    const unsigned long long q01 = ((unsigned long long)qww.y << 32) | qww.x;

    float acc[2][8][4];
#pragma unroll
    for (int i = 0; i < 2; i++)
#pragma unroll
        for (int j = 0; j < 8; j++)
#pragma unroll
            for (int r = 0; r < 4; r++) acc[i][j][r] = 0.f;
    float ssum = 0.f;

    auto loadV = [&](int c) {
        __half* dvh = sVh + (c & 1) * 64 * 72;
        const size_t gb = ((size_t)(b * S_ + c * 64)) * D_ + h * HD_;
#pragma unroll
        for (int i = 0; i < 4; i++) {
            int id = i * 128 + t;
            int r  = id >> 3, ch = id & 7;
            cpa16(smem_u32(dvh + r * 72 + ch * 8), Vh + gb + (size_t)r * D_ + ch * 8);
        }
    };

#pragma unroll
    for (int i = 0; i < 8; i++) {
        int j = i * 128 + t;
        *(uint2*)&sKb[j * 2] = *(const uint2*)&kbits[((size_t)(b * S_ + j)) * 32 + h * 2];
    }
    if (t < 65) sLut[t] = __expf((float)t * 0.125f);

    loadV(0);
    asm volatile("cp.async.commit_group;" ::: "memory");

    const unsigned* mrow = mbits + b * 32 * S_ + qblk * 128 + t;
    unsigned mw0 = mrow[0];
    unsigned mw1 = mrow[S_];
    __syncthreads();

    for (int c = 0; c < 16; c++) {
        const int k0 = c * 64;

        if (c + 1 < 16) loadV(c + 1);
        asm volatile("cp.async.commit_group;" ::: "memory");
        unsigned mn0 = 0u, mn1 = 0u;
        if (c + 1 < 16) {
            mn0 = mrow[(size_t)(2 * c + 2) * S_];
            mn1 = mrow[(size_t)(2 * c + 3) * S_];
        }

        {
            __half* ph = sPh + t * 72;
            const unsigned long long* kb64 = (const unsigned long long*)sKb;
#pragma unroll
            for (int j = 0; j < 64; j += 2) {
                const unsigned mwv = (j < 32) ? mw0 : mw1;
                const int jj = j & 31;
                int s0 = __popcll(q01 & kb64[k0 + j]);
                int s1 = __popcll(q01 & kb64[k0 + j + 1]);
                float e0 = sLut[s0 * (int)((mwv >> jj) & 1u)];
                float e1 = sLut[s1 * (int)((mwv >> (jj + 1)) & 1u)];
                __half h0 = __float2half_rn(e0), h1 = __float2half_rn(e1);
                ssum += __half2float(h0) + __half2float(h1);
                *(unsigned*)(ph + j) = packh2(h0, h1);
            }
        }
        mw0 = mn0; mw1 = mn1;
        __syncthreads();
        asm volatile("cp.async.wait_group 1;" ::: "memory");

        const __half* vhb = sVh + (c & 1) * 64 * 72;
        const int lr  = lane & 15;
        const int lc8 = (lane >> 4) * 8;
        const int l8  = lane & 7;
        const int ks8 = ((lane >> 3) & 1) * 8;
        const int ns8 = (lane >> 4) * 8;
#pragma unroll
        for (int kk = 0; kk < 4; kk++) {
            unsigned ah[2][4];
#pragma unroll
            for (int mi = 0; mi < 2; mi++) {
                const int rofs = (wid * 32 + mi * 16 + lr) * 72 + kk * 16 + lc8;
                ldm4(ah[mi], sPh + rofs);
            }
            unsigned vh[4][4];
#pragma unroll
            for (int nb = 0; nb < 4; nb++) {
                const int vofs = (kk * 16 + ks8 + l8) * 72 + nb * 16 + ns8;
                ldm4t(vh[nb], vhb + vofs);
            }
#pragma unroll
            for (int mi = 0; mi < 2; mi++) {
#pragma unroll
                for (int nj = 0; nj < 8; nj++) {
                    const int nb = nj >> 1, half = nj & 1;
                    mma16816(acc[mi][nj], ah[mi], vh[nb][half * 2], vh[nb][half * 2 + 1]);
                }
            }
        }
        __syncthreads();
    }

    sSum[t] = ssum;
    __syncthreads();

    const int g = lane >> 2, tg = lane & 3;
#pragma unroll
    for (int mi = 0; mi < 2; mi++) {
        const int qr0 = wid * 32 + mi * 16 + g;
        const float inv0 = 1.f / sSum[qr0];
        const float inv1 = 1.f / sSum[qr0 + 8];
        const size_t base0 = ((size_t)(b * S_ + qblk * 128 + qr0)) * D_ + h * HD_;
#pragma unroll
        for (int nj = 0; nj < 8; nj++) {
            const int n = nj * 8 + tg * 2;
            float v0 = acc[mi][nj][0] * inv0;
            float v1 = acc[mi][nj][1] * inv0;
            float v2 = acc[mi][nj][2] * inv1;
            float v3 = acc[mi][nj][3] * inv1;
            *(unsigned*)(outh + base0 + n)          = packh2(__float2half_rn(v0), __float2half_rn(v1));
            *(unsigned*)(outh + base0 + 8 * D_ + n) = packh2(__float2half_rn(v2), __float2half_rn(v3));
        }
    }
}

// ---------------- launch ----------------
extern "C" void kernel_launch(void* const* d_in, const int* in_sizes, int n_in,
                              void* d_out, int out_size)
{
    const float* Q   = (const float*)d_in[0];
    const float* K_  = (const float*)d_in[1];
    const float* adj = (const float*)d_in[2];
    const float* Wq  = (const float*)d_in[3];
    const float* bq  = (const float*)d_in[4];
    const float* Wk  = (const float*)d_in[5];
    const float* bk  = (const float*)d_in[6];
    const float* Wv  = (const float*)d_in[7];
    const float* bv  = (const float*)d_in[8];
    const float* Wo  = (const float*)d_in[9];
    const float* bo  = (const float*)d_in[10];
    const float* gq  = (const float*)d_in[11];
    const float* beq = (const float*)d_in[12];
    const float* gk  = (const float*)d_in[13];
    const float* bek = (const float*)d_in[14];
    float* out = (float*)d_out;

    float *mursq, *mursk;
    __half *Xqh, *Xkh, *Qb, *Kb, *Ath, *Vh, *Wq1, *Wk1, *Wv1, *Wo1;
    unsigned *qb, *kb, *mb, *flagq, *flagk;
    int* cnt;
    cudaGetSymbolAddress((void**)&Xqh,  g_Xqh);
    cudaGetSymbolAddress((void**)&Xkh,  g_Xkh);
    cudaGetSymbolAddress((void**)&Qb,   g_Qb);
    cudaGetSymbolAddress((void**)&Kb,   g_Kb);
    cudaGetSymbolAddress((void**)&Ath,  g_Ath);
    cudaGetSymbolAddress((void**)&Vh,   g_Vh);
    cudaGetSymbolAddress((void**)&Wq1,  g_Wq1);
    cudaGetSymbolAddress((void**)&Wk1,  g_Wk1);
    cudaGetSymbolAddress((void**)&Wv1,  g_Wv1);
    cudaGetSymbolAddress((void**)&Wo1,  g_Wo1);
    cudaGetSymbolAddress((void**)&qb,   g_qb);
    cudaGetSymbolAddress((void**)&kb,   g_kb);
    cudaGetSymbolAddress((void**)&mb,   g_mb);
    cudaGetSymbolAddress((void**)&mursq, g_mursq);
    cudaGetSymbolAddress((void**)&mursk, g_mursk);
    cudaGetSymbolAddress((void**)&flagq, g_flagq);
    cudaGetSymbolAddress((void**)&flagk, g_flagk);
    cudaGetSymbolAddress((void**)&cnt,   g_cnt);

    // one-time stream/event setup (host-side objects; identical launch graph every call)
    static cudaStream_t s2 = nullptr;
    static cudaEvent_t ev0 = nullptr, evA = nullptr, evB = nullptr;
    if (s2 == nullptr) {
        cudaStreamCreateWithFlags(&s2, cudaStreamNonBlocking);
        cudaEventCreateWithFlags(&ev0, cudaEventDisableTiming);
        cudaEventCreateWithFlags(&evA, cudaEventDisableTiming);
        cudaEventCreateWithFlags(&evB, cudaEventDisableTiming);
    }

    const int smem1 = 3 * 2 * TILEB + 1024;
    cudaFuncSetAttribute((const void*)gemm3,
                         cudaFuncAttributeMaxDynamicSharedMemorySize, smem1);
    cudaFuncSetAttribute((const void*)hgemm_o<3>,
                         cudaFuncAttributeMaxDynamicSharedMemorySize, smem1);
    cudaFuncSetAttribute((const void*)attn_kernel,
                         cudaFuncAttributeMaxDynamicSharedMemorySize, AT_SMEM);

    const int WELEM = D_ * D_;

    // fork s2 from stream 0
    cudaEventRecord(ev0, 0);
    cudaStreamWaitEvent(s2, ev0, 0);

    // s2: mask bit-pack (independent until attention)
    prep_mask<<<B_ * 32 * S_ / 256, 256, 0, s2>>>(adj, mb);

    // stream 0: weight + input prep
    prep_w4<<<dim3(WELEM / 4 / 256, 4), 256>>>(Wq, Wk, Wv, Wo, Wq1, Wk1, Wv1, Wo1);
    prep_bin2<<<dim3(ROWS * D_ / 4 / 256, 2), 256>>>(Q, K_, Qb, Kb, cnt);

    // s2 also needs Kb + Wv1 ready for the V GEMM
    cudaEventRecord(evA, 0);
    cudaStreamWaitEvent(s2, evA, 0);

    // s2: V projection (z = 2)
    gemm3<<<dim3(D_ / 128, ROWS / 128, 1), 256, smem1, s2>>>(
        Qb, Kb, Wq1, Wk1, Wv1, bq, bk, bv, Xqh, Xkh, Vh, 2);
    cudaEventRecord(evB, s2);

    // stream 0: Q/K projections (z = 0,1), then LN/LIF + fixup
    gemm3<<<dim3(D_ / 128, ROWS / 128, 2), 256, smem1>>>(
        Qb, Kb, Wq1, Wk1, Wv1, bq, bk, bv, Xqh, Xkh, Vh, 0);

    ln_lif2<<<dim3(ROWS, 2), 256>>>(Xqh, Xkh, gq, beq, gk, bek,
                                    qb, kb, mursq, mursk, flagq, flagk, cnt);

    fixup2<<<dim3(FIX_WARPS / 4, 2), 128>>>(Q, K_, Wq, Wk, bq, bk,
                                            gq, beq, gk, bek, mursq, mursk,
                                            flagq, flagk, cnt, qb, kb);

    // join: attention needs Vh (s2) and mb (s2)
    cudaStreamWaitEvent(0, evB, 0);

    attn_kernel<<<dim3(8, H_, B_), 128, AT_SMEM>>>(qb, kb, Vh, mb, Ath);

    hgemm_o<3><<<dim3(D_ / 128, ROWS / 128), 256, smem1>>>(Ath, Wo1, bo, Ath, out);
}